// round 1
// baseline (speedup 1.0000x reference)
#include <cuda_runtime.h>

// ---------------------------------------------------------------------------
// BertBiAttention: two-stream cross attention + output proj + residual LN.
// B=4, S=2048, HID=768, H=12, HD=64. FP32 baseline (round 1).
// ---------------------------------------------------------------------------

constexpr int B = 4, S = 2048, HID = 768, H = 12, HD = 64;
constexpr int M = B * S;                      // 8192 rows
constexpr size_t MAT = (size_t)M * HID;       // 6,291,456 floats per [B,S,HID]

// Scratch: q1,k1,v1,q2,k2,v2,ctx1,ctx2,t1,t2  (10 buffers)
__device__ float g_scratch[10 * 6291456];

// ---------------------------------------------------------------------------
// SGEMM: C[M,768] = A[M,768] @ W[768,768] + bias[768]
// 64x64 tile, BK=16, 256 threads, 4x4 register tile per thread.
// ---------------------------------------------------------------------------
__global__ void __launch_bounds__(256) sgemm_bias_kernel(
    const float* __restrict__ A, const float* __restrict__ W,
    const float* __restrict__ bias, float* __restrict__ C)
{
    __shared__ float As[16][68];   // A transposed: As[k][m]
    __shared__ float Bs[16][68];   // Bs[k][n]

    const int tid = threadIdx.x;
    const int tx = tid & 15, ty = tid >> 4;
    const int row0 = blockIdx.y * 64, col0 = blockIdx.x * 64;

    float acc[16];
#pragma unroll
    for (int i = 0; i < 16; i++) acc[i] = 0.f;

    const int lm = tid >> 2, lk4 = (tid & 3) << 2;   // A-tile load mapping
    const int lk = tid >> 4, ln4 = (tid & 15) << 2;  // B-tile load mapping

    for (int k0 = 0; k0 < 768; k0 += 16) {
        float4 a4 = *(const float4*)(A + (size_t)(row0 + lm) * 768 + k0 + lk4);
        float4 b4 = *(const float4*)(W + (size_t)(k0 + lk) * 768 + col0 + ln4);
        As[lk4 + 0][lm] = a4.x;
        As[lk4 + 1][lm] = a4.y;
        As[lk4 + 2][lm] = a4.z;
        As[lk4 + 3][lm] = a4.w;
        *(float4*)&Bs[lk][ln4] = b4;
        __syncthreads();
#pragma unroll
        for (int k = 0; k < 16; k++) {
            float4 av = *(const float4*)&As[k][ty * 4];
            float4 bv = *(const float4*)&Bs[k][tx * 4];
            acc[0]  += av.x * bv.x; acc[1]  += av.x * bv.y;
            acc[2]  += av.x * bv.z; acc[3]  += av.x * bv.w;
            acc[4]  += av.y * bv.x; acc[5]  += av.y * bv.y;
            acc[6]  += av.y * bv.z; acc[7]  += av.y * bv.w;
            acc[8]  += av.z * bv.x; acc[9]  += av.z * bv.y;
            acc[10] += av.z * bv.z; acc[11] += av.z * bv.w;
            acc[12] += av.w * bv.x; acc[13] += av.w * bv.y;
            acc[14] += av.w * bv.z; acc[15] += av.w * bv.w;
        }
        __syncthreads();
    }

    float4 bias4 = *(const float4*)(bias + col0 + tx * 4);
#pragma unroll
    for (int i = 0; i < 4; i++) {
        float4 o;
        o.x = acc[i * 4 + 0] + bias4.x;
        o.y = acc[i * 4 + 1] + bias4.y;
        o.z = acc[i * 4 + 2] + bias4.z;
        o.w = acc[i * 4 + 3] + bias4.w;
        *(float4*)(C + (size_t)(row0 + ty * 4 + i) * 768 + col0 + tx * 4) = o;
    }
}

// ---------------------------------------------------------------------------
// Flash attention: O = softmax(Q K^T / 8 + mask) V  per (b, h).
// BM=64 q-rows, BN=64 keys, HD=64. 256 threads: thread = (row r, tx in 0..3),
// each thread owns 16 score cols / 16 out dims at positions tx*4 + cc*16 + j.
// K tile stored transposed in smem; KV buffer reused for V.
// ---------------------------------------------------------------------------
constexpr int FLASH_SMEM_BYTES = (64 * 65 + 64 * 68 + 64 * 68) * 4;  // 51456

__global__ void __launch_bounds__(256) flash_attn_kernel(
    const float* __restrict__ Q, const float* __restrict__ K,
    const float* __restrict__ V, const float* __restrict__ mask,
    float* __restrict__ O)
{
    extern __shared__ float sm[];
    float* Qs  = sm;                 // [64][65] scalar reads (odd stride: no conflicts)
    float* KVs = sm + 64 * 65;       // [64][68] K transposed [d][c], then V [c][d]
    float* Ps  = KVs + 64 * 68;      // [64][68] probabilities

    const int tid = threadIdx.x;
    const int r  = tid >> 2;         // query row 0..63
    const int tx = tid & 3;
    const int q0 = blockIdx.x * 64;
    const int h  = blockIdx.y;
    const int b  = blockIdx.z;

    // Load Q tile [64 x 64], scalar stores into stride-65 rows.
    const float* Qb = Q + ((size_t)(b * S + q0)) * HID + h * HD;
    for (int idx = tid; idx < 64 * 16; idx += 256) {
        int row = idx >> 4, c4 = (idx & 15) << 2;
        float4 v = *(const float4*)(Qb + (size_t)row * HID + c4);
        Qs[row * 65 + c4 + 0] = v.x;
        Qs[row * 65 + c4 + 1] = v.y;
        Qs[row * 65 + c4 + 2] = v.z;
        Qs[row * 65 + c4 + 3] = v.w;
    }

    float mrun = -1e30f, lrun = 0.f;
    float o[16];
#pragma unroll
    for (int i = 0; i < 16; i++) o[i] = 0.f;

    const float* mb = mask + (size_t)b * S;

    for (int k0 = 0; k0 < S; k0 += 64) {
        __syncthreads();   // previous PV reads of KVs done
        // Load K transposed: KVs[d][c] = K[k0+c][d]
        const float* Kb = K + ((size_t)(b * S + k0)) * HID + h * HD;
        for (int idx = tid; idx < 64 * 16; idx += 256) {
            int c = idx >> 4, d4 = (idx & 15) << 2;
            float4 v = *(const float4*)(Kb + (size_t)c * HID + d4);
            KVs[(d4 + 0) * 68 + c] = v.x;
            KVs[(d4 + 1) * 68 + c] = v.y;
            KVs[(d4 + 2) * 68 + c] = v.z;
            KVs[(d4 + 3) * 68 + c] = v.w;
        }
        __syncthreads();

        // S = Q K^T  (16 cols per thread)
        float s[16];
#pragma unroll
        for (int i = 0; i < 16; i++) s[i] = 0.f;
#pragma unroll 8
        for (int d = 0; d < 64; d++) {
            float qv = Qs[r * 65 + d];
            const float* Kr = KVs + d * 68 + tx * 4;
#pragma unroll
            for (int cc = 0; cc < 4; cc++) {
                float4 kv = *(const float4*)(Kr + cc * 16);
                s[cc * 4 + 0] += qv * kv.x;
                s[cc * 4 + 1] += qv * kv.y;
                s[cc * 4 + 2] += qv * kv.z;
                s[cc * 4 + 3] += qv * kv.w;
            }
        }

        // scale + additive mask; local max
        float mloc = -1e30f;
#pragma unroll
        for (int cc = 0; cc < 4; cc++)
#pragma unroll
            for (int j = 0; j < 4; j++) {
                int c = tx * 4 + cc * 16 + j;
                float val = s[cc * 4 + j] * 0.125f + mb[k0 + c];
                s[cc * 4 + j] = val;
                mloc = fmaxf(mloc, val);
            }
        // reduce across the 4 lanes sharing a row (adjacent lanes)
        mloc = fmaxf(mloc, __shfl_xor_sync(0xffffffffu, mloc, 1));
        mloc = fmaxf(mloc, __shfl_xor_sync(0xffffffffu, mloc, 2));
        float mnew = fmaxf(mrun, mloc);
        float alpha = __expf(mrun - mnew);

        float lloc = 0.f;
#pragma unroll
        for (int i = 0; i < 16; i++) {
            float p = __expf(s[i] - mnew);
            s[i] = p;
            lloc += p;
        }
        // write P tile
#pragma unroll
        for (int cc = 0; cc < 4; cc++) {
            float4 p4 = make_float4(s[cc * 4 + 0], s[cc * 4 + 1],
                                    s[cc * 4 + 2], s[cc * 4 + 3]);
            *(float4*)(Ps + r * 68 + tx * 4 + cc * 16) = p4;
        }
        lloc += __shfl_xor_sync(0xffffffffu, lloc, 1);
        lloc += __shfl_xor_sync(0xffffffffu, lloc, 2);
        lrun = lrun * alpha + lloc;
        mrun = mnew;
#pragma unroll
        for (int i = 0; i < 16; i++) o[i] *= alpha;

        __syncthreads();   // P written, K reads done -> safe to overwrite KVs
        // Load V natural layout: KVs[c][d]
        const float* Vb = V + ((size_t)(b * S + k0)) * HID + h * HD;
        for (int idx = tid; idx < 64 * 16; idx += 256) {
            int c = idx >> 4, d4 = (idx & 15) << 2;
            float4 v = *(const float4*)(Vb + (size_t)c * HID + d4);
            *(float4*)(KVs + c * 68 + d4) = v;
        }
        __syncthreads();

        // O += P V
#pragma unroll 8
        for (int c = 0; c < 64; c++) {
            float p = Ps[r * 68 + c];
            const float* Vr = KVs + c * 68 + tx * 4;
#pragma unroll
            for (int cc = 0; cc < 4; cc++) {
                float4 vv = *(const float4*)(Vr + cc * 16);
                o[cc * 4 + 0] += p * vv.x;
                o[cc * 4 + 1] += p * vv.y;
                o[cc * 4 + 2] += p * vv.z;
                o[cc * 4 + 3] += p * vv.w;
            }
        }
    }

    float inv = 1.f / lrun;
    float* Ob = O + ((size_t)(b * S + q0 + r)) * HID + h * HD + tx * 4;
#pragma unroll
    for (int cc = 0; cc < 4; cc++) {
        float4 ov = make_float4(o[cc * 4 + 0] * inv, o[cc * 4 + 1] * inv,
                                o[cc * 4 + 2] * inv, o[cc * 4 + 3] * inv);
        *(float4*)(Ob + cc * 16) = ov;
    }
}

// ---------------------------------------------------------------------------
// out = LayerNorm(T + residual) * g + b   (one row of 768 per block)
// ---------------------------------------------------------------------------
__global__ void __launch_bounds__(256) add_ln_kernel(
    const float* __restrict__ T, const float* __restrict__ Rsd,
    const float* __restrict__ g, const float* __restrict__ bb,
    float* __restrict__ out)
{
    const int row = blockIdx.x;
    const int t = threadIdx.x;
    const float* Tr = T + (size_t)row * 768;
    const float* Rr = Rsd + (size_t)row * 768;

    float x[3];
    float sum = 0.f, sq = 0.f;
#pragma unroll
    for (int i = 0; i < 3; i++) {
        int c = t + i * 256;
        x[i] = Tr[c] + Rr[c];
        sum += x[i];
        sq += x[i] * x[i];
    }

    __shared__ float sa[8], sb[8];
#pragma unroll
    for (int off = 16; off; off >>= 1) {
        sum += __shfl_down_sync(0xffffffffu, sum, off);
        sq  += __shfl_down_sync(0xffffffffu, sq,  off);
    }
    int w = t >> 5, lane = t & 31;
    if (lane == 0) { sa[w] = sum; sb[w] = sq; }
    __syncthreads();
    if (t < 32) {
        sum = (t < 8) ? sa[t] : 0.f;
        sq  = (t < 8) ? sb[t] : 0.f;
#pragma unroll
        for (int off = 4; off; off >>= 1) {
            sum += __shfl_down_sync(0xffffffffu, sum, off);
            sq  += __shfl_down_sync(0xffffffffu, sq,  off);
        }
        if (t == 0) { sa[0] = sum; sb[0] = sq; }
    }
    __syncthreads();
    sum = sa[0]; sq = sb[0];

    float mu  = sum * (1.f / 768.f);
    float var = sq * (1.f / 768.f) - mu * mu;
    float rstd = rsqrtf(var + 1e-12f);
#pragma unroll
    for (int i = 0; i < 3; i++) {
        int c = t + i * 256;
        out[(size_t)row * 768 + c] = (x[i] - mu) * rstd * g[c] + bb[c];
    }
}

// ---------------------------------------------------------------------------
extern "C" void kernel_launch(void* const* d_in, const int* in_sizes, int n_in,
                              void* d_out, int out_size)
{
    const float* x1    = (const float*)d_in[0];
    const float* mask1 = (const float*)d_in[1];
    const float* x2    = (const float*)d_in[2];
    const float* mask2 = (const float*)d_in[3];
    const float* q1w = (const float*)d_in[4];  const float* q1b = (const float*)d_in[5];
    const float* k1w = (const float*)d_in[6];  const float* k1b = (const float*)d_in[7];
    const float* v1w = (const float*)d_in[8];  const float* v1b = (const float*)d_in[9];
    const float* q2w = (const float*)d_in[10]; const float* q2b = (const float*)d_in[11];
    const float* k2w = (const float*)d_in[12]; const float* k2b = (const float*)d_in[13];
    const float* v2w = (const float*)d_in[14]; const float* v2b = (const float*)d_in[15];
    const float* d1w = (const float*)d_in[16]; const float* d1b = (const float*)d_in[17];
    const float* d2w = (const float*)d_in[18]; const float* d2b = (const float*)d_in[19];
    const float* ln1g = (const float*)d_in[20]; const float* ln1b = (const float*)d_in[21];
    const float* ln2g = (const float*)d_in[22]; const float* ln2b = (const float*)d_in[23];

    void* sp = nullptr;
    cudaGetSymbolAddress(&sp, g_scratch);
    float* base = (float*)sp;
    float* q1   = base + 0 * MAT;
    float* k1   = base + 1 * MAT;
    float* v1   = base + 2 * MAT;
    float* q2   = base + 3 * MAT;
    float* k2   = base + 4 * MAT;
    float* v2   = base + 5 * MAT;
    float* ctx1 = base + 6 * MAT;
    float* ctx2 = base + 7 * MAT;
    float* t1   = base + 8 * MAT;
    float* t2   = base + 9 * MAT;

    float* out1 = (float*)d_out;
    float* out2 = out1 + MAT;

    dim3 gg(12, 128);  // 768/64 cols x 8192/64 rows
    sgemm_bias_kernel<<<gg, 256>>>(x1, q1w, q1b, q1);
    sgemm_bias_kernel<<<gg, 256>>>(x1, k1w, k1b, k1);
    sgemm_bias_kernel<<<gg, 256>>>(x1, v1w, v1b, v1);
    sgemm_bias_kernel<<<gg, 256>>>(x2, q2w, q2b, q2);
    sgemm_bias_kernel<<<gg, 256>>>(x2, k2w, k2b, k2);
    sgemm_bias_kernel<<<gg, 256>>>(x2, v2w, v2b, v2);

    cudaFuncSetAttribute(flash_attn_kernel,
                         cudaFuncAttributeMaxDynamicSharedMemorySize,
                         FLASH_SMEM_BYTES);
    dim3 fg(S / 64, H, B);
    // ctx1: queries from stream2 attend K1/V1 with mask1
    flash_attn_kernel<<<fg, 256, FLASH_SMEM_BYTES>>>(q2, k1, v1, mask1, ctx1);
    // ctx2: queries from stream1 attend K2/V2 with mask2
    flash_attn_kernel<<<fg, 256, FLASH_SMEM_BYTES>>>(q1, k2, v2, mask2, ctx2);

    sgemm_bias_kernel<<<gg, 256>>>(ctx1, d1w, d1b, t1);
    sgemm_bias_kernel<<<gg, 256>>>(ctx2, d2w, d2b, t2);

    add_ln_kernel<<<M, 256>>>(t1, x1, ln1g, ln1b, out1);
    add_ln_kernel<<<M, 256>>>(t2, x2, ln2g, ln2b, out2);
}

// round 2
// speedup vs baseline: 1.0005x; 1.0005x over previous
#include <cuda_runtime.h>

// ---------------------------------------------------------------------------
// BertBiAttention: two-stream cross attention + output proj + residual LN.
// B=4, S=2048, HID=768, H=12, HD=64. FP32 baseline (round 1).
// ---------------------------------------------------------------------------

constexpr int B = 4, S = 2048, HID = 768, H = 12, HD = 64;
constexpr int M = B * S;                      // 8192 rows
constexpr size_t MAT = (size_t)M * HID;       // 6,291,456 floats per [B,S,HID]

// Scratch: q1,k1,v1,q2,k2,v2,ctx1,ctx2,t1,t2  (10 buffers)
__device__ float g_scratch[10 * 6291456];

// ---------------------------------------------------------------------------
// SGEMM: C[M,768] = A[M,768] @ W[768,768] + bias[768]
// 64x64 tile, BK=16, 256 threads, 4x4 register tile per thread.
// ---------------------------------------------------------------------------
__global__ void __launch_bounds__(256) sgemm_bias_kernel(
    const float* __restrict__ A, const float* __restrict__ W,
    const float* __restrict__ bias, float* __restrict__ C)
{
    __shared__ float As[16][68];   // A transposed: As[k][m]
    __shared__ float Bs[16][68];   // Bs[k][n]

    const int tid = threadIdx.x;
    const int tx = tid & 15, ty = tid >> 4;
    const int row0 = blockIdx.y * 64, col0 = blockIdx.x * 64;

    float acc[16];
#pragma unroll
    for (int i = 0; i < 16; i++) acc[i] = 0.f;

    const int lm = tid >> 2, lk4 = (tid & 3) << 2;   // A-tile load mapping
    const int lk = tid >> 4, ln4 = (tid & 15) << 2;  // B-tile load mapping

    for (int k0 = 0; k0 < 768; k0 += 16) {
        float4 a4 = *(const float4*)(A + (size_t)(row0 + lm) * 768 + k0 + lk4);
        float4 b4 = *(const float4*)(W + (size_t)(k0 + lk) * 768 + col0 + ln4);
        As[lk4 + 0][lm] = a4.x;
        As[lk4 + 1][lm] = a4.y;
        As[lk4 + 2][lm] = a4.z;
        As[lk4 + 3][lm] = a4.w;
        *(float4*)&Bs[lk][ln4] = b4;
        __syncthreads();
#pragma unroll
        for (int k = 0; k < 16; k++) {
            float4 av = *(const float4*)&As[k][ty * 4];
            float4 bv = *(const float4*)&Bs[k][tx * 4];
            acc[0]  += av.x * bv.x; acc[1]  += av.x * bv.y;
            acc[2]  += av.x * bv.z; acc[3]  += av.x * bv.w;
            acc[4]  += av.y * bv.x; acc[5]  += av.y * bv.y;
            acc[6]  += av.y * bv.z; acc[7]  += av.y * bv.w;
            acc[8]  += av.z * bv.x; acc[9]  += av.z * bv.y;
            acc[10] += av.z * bv.z; acc[11] += av.z * bv.w;
            acc[12] += av.w * bv.x; acc[13] += av.w * bv.y;
            acc[14] += av.w * bv.z; acc[15] += av.w * bv.w;
        }
        __syncthreads();
    }

    float4 bias4 = *(const float4*)(bias + col0 + tx * 4);
#pragma unroll
    for (int i = 0; i < 4; i++) {
        float4 o;
        o.x = acc[i * 4 + 0] + bias4.x;
        o.y = acc[i * 4 + 1] + bias4.y;
        o.z = acc[i * 4 + 2] + bias4.z;
        o.w = acc[i * 4 + 3] + bias4.w;
        *(float4*)(C + (size_t)(row0 + ty * 4 + i) * 768 + col0 + tx * 4) = o;
    }
}

// ---------------------------------------------------------------------------
// Flash attention: O = softmax(Q K^T / 8 + mask) V  per (b, h).
// BM=64 q-rows, BN=64 keys, HD=64. 256 threads: thread = (row r, tx in 0..3),
// each thread owns 16 score cols / 16 out dims at positions tx*4 + cc*16 + j.
// K tile stored transposed in smem; KV buffer reused for V.
// ---------------------------------------------------------------------------
constexpr int FLASH_SMEM_BYTES = (64 * 65 + 64 * 68 + 64 * 68) * 4;  // 51456

__global__ void __launch_bounds__(256) flash_attn_kernel(
    const float* __restrict__ Q, const float* __restrict__ K,
    const float* __restrict__ V, const float* __restrict__ mask,
    float* __restrict__ O)
{
    extern __shared__ float sm[];
    float* Qs  = sm;                 // [64][65] scalar reads (odd stride: no conflicts)
    float* KVs = sm + 64 * 65;       // [64][68] K transposed [d][c], then V [c][d]
    float* Ps  = KVs + 64 * 68;      // [64][68] probabilities

    const int tid = threadIdx.x;
    const int r  = tid >> 2;         // query row 0..63
    const int tx = tid & 3;
    const int q0 = blockIdx.x * 64;
    const int h  = blockIdx.y;
    const int b  = blockIdx.z;

    // Load Q tile [64 x 64], scalar stores into stride-65 rows.
    const float* Qb = Q + ((size_t)(b * S + q0)) * HID + h * HD;
    for (int idx = tid; idx < 64 * 16; idx += 256) {
        int row = idx >> 4, c4 = (idx & 15) << 2;
        float4 v = *(const float4*)(Qb + (size_t)row * HID + c4);
        Qs[row * 65 + c4 + 0] = v.x;
        Qs[row * 65 + c4 + 1] = v.y;
        Qs[row * 65 + c4 + 2] = v.z;
        Qs[row * 65 + c4 + 3] = v.w;
    }

    float mrun = -1e30f, lrun = 0.f;
    float o[16];
#pragma unroll
    for (int i = 0; i < 16; i++) o[i] = 0.f;

    const float* mb = mask + (size_t)b * S;

    for (int k0 = 0; k0 < S; k0 += 64) {
        __syncthreads();   // previous PV reads of KVs done
        // Load K transposed: KVs[d][c] = K[k0+c][d]
        const float* Kb = K + ((size_t)(b * S + k0)) * HID + h * HD;
        for (int idx = tid; idx < 64 * 16; idx += 256) {
            int c = idx >> 4, d4 = (idx & 15) << 2;
            float4 v = *(const float4*)(Kb + (size_t)c * HID + d4);
            KVs[(d4 + 0) * 68 + c] = v.x;
            KVs[(d4 + 1) * 68 + c] = v.y;
            KVs[(d4 + 2) * 68 + c] = v.z;
            KVs[(d4 + 3) * 68 + c] = v.w;
        }
        __syncthreads();

        // S = Q K^T  (16 cols per thread)
        float s[16];
#pragma unroll
        for (int i = 0; i < 16; i++) s[i] = 0.f;
#pragma unroll 8
        for (int d = 0; d < 64; d++) {
            float qv = Qs[r * 65 + d];
            const float* Kr = KVs + d * 68 + tx * 4;
#pragma unroll
            for (int cc = 0; cc < 4; cc++) {
                float4 kv = *(const float4*)(Kr + cc * 16);
                s[cc * 4 + 0] += qv * kv.x;
                s[cc * 4 + 1] += qv * kv.y;
                s[cc * 4 + 2] += qv * kv.z;
                s[cc * 4 + 3] += qv * kv.w;
            }
        }

        // scale + additive mask; local max
        float mloc = -1e30f;
#pragma unroll
        for (int cc = 0; cc < 4; cc++)
#pragma unroll
            for (int j = 0; j < 4; j++) {
                int c = tx * 4 + cc * 16 + j;
                float val = s[cc * 4 + j] * 0.125f + mb[k0 + c];
                s[cc * 4 + j] = val;
                mloc = fmaxf(mloc, val);
            }
        // reduce across the 4 lanes sharing a row (adjacent lanes)
        mloc = fmaxf(mloc, __shfl_xor_sync(0xffffffffu, mloc, 1));
        mloc = fmaxf(mloc, __shfl_xor_sync(0xffffffffu, mloc, 2));
        float mnew = fmaxf(mrun, mloc);
        float alpha = __expf(mrun - mnew);

        float lloc = 0.f;
#pragma unroll
        for (int i = 0; i < 16; i++) {
            float p = __expf(s[i] - mnew);
            s[i] = p;
            lloc += p;
        }
        // write P tile
#pragma unroll
        for (int cc = 0; cc < 4; cc++) {
            float4 p4 = make_float4(s[cc * 4 + 0], s[cc * 4 + 1],
                                    s[cc * 4 + 2], s[cc * 4 + 3]);
            *(float4*)(Ps + r * 68 + tx * 4 + cc * 16) = p4;
        }
        lloc += __shfl_xor_sync(0xffffffffu, lloc, 1);
        lloc += __shfl_xor_sync(0xffffffffu, lloc, 2);
        lrun = lrun * alpha + lloc;
        mrun = mnew;
#pragma unroll
        for (int i = 0; i < 16; i++) o[i] *= alpha;

        __syncthreads();   // P written, K reads done -> safe to overwrite KVs
        // Load V natural layout: KVs[c][d]
        const float* Vb = V + ((size_t)(b * S + k0)) * HID + h * HD;
        for (int idx = tid; idx < 64 * 16; idx += 256) {
            int c = idx >> 4, d4 = (idx & 15) << 2;
            float4 v = *(const float4*)(Vb + (size_t)c * HID + d4);
            *(float4*)(KVs + c * 68 + d4) = v;
        }
        __syncthreads();

        // O += P V
#pragma unroll 8
        for (int c = 0; c < 64; c++) {
            float p = Ps[r * 68 + c];
            const float* Vr = KVs + c * 68 + tx * 4;
#pragma unroll
            for (int cc = 0; cc < 4; cc++) {
                float4 vv = *(const float4*)(Vr + cc * 16);
                o[cc * 4 + 0] += p * vv.x;
                o[cc * 4 + 1] += p * vv.y;
                o[cc * 4 + 2] += p * vv.z;
                o[cc * 4 + 3] += p * vv.w;
            }
        }
    }

    float inv = 1.f / lrun;
    float* Ob = O + ((size_t)(b * S + q0 + r)) * HID + h * HD + tx * 4;
#pragma unroll
    for (int cc = 0; cc < 4; cc++) {
        float4 ov = make_float4(o[cc * 4 + 0] * inv, o[cc * 4 + 1] * inv,
                                o[cc * 4 + 2] * inv, o[cc * 4 + 3] * inv);
        *(float4*)(Ob + cc * 16) = ov;
    }
}

// ---------------------------------------------------------------------------
// out = LayerNorm(T + residual) * g + b   (one row of 768 per block)
// ---------------------------------------------------------------------------
__global__ void __launch_bounds__(256) add_ln_kernel(
    const float* __restrict__ T, const float* __restrict__ Rsd,
    const float* __restrict__ g, const float* __restrict__ bb,
    float* __restrict__ out)
{
    const int row = blockIdx.x;
    const int t = threadIdx.x;
    const float* Tr = T + (size_t)row * 768;
    const float* Rr = Rsd + (size_t)row * 768;

    float x[3];
    float sum = 0.f, sq = 0.f;
#pragma unroll
    for (int i = 0; i < 3; i++) {
        int c = t + i * 256;
        x[i] = Tr[c] + Rr[c];
        sum += x[i];
        sq += x[i] * x[i];
    }

    __shared__ float sa[8], sb[8];
#pragma unroll
    for (int off = 16; off; off >>= 1) {
        sum += __shfl_down_sync(0xffffffffu, sum, off);
        sq  += __shfl_down_sync(0xffffffffu, sq,  off);
    }
    int w = t >> 5, lane = t & 31;
    if (lane == 0) { sa[w] = sum; sb[w] = sq; }
    __syncthreads();
    if (t < 32) {
        sum = (t < 8) ? sa[t] : 0.f;
        sq  = (t < 8) ? sb[t] : 0.f;
#pragma unroll
        for (int off = 4; off; off >>= 1) {
            sum += __shfl_down_sync(0xffffffffu, sum, off);
            sq  += __shfl_down_sync(0xffffffffu, sq,  off);
        }
        if (t == 0) { sa[0] = sum; sb[0] = sq; }
    }
    __syncthreads();
    sum = sa[0]; sq = sb[0];

    float mu  = sum * (1.f / 768.f);
    float var = sq * (1.f / 768.f) - mu * mu;
    float rstd = rsqrtf(var + 1e-12f);
#pragma unroll
    for (int i = 0; i < 3; i++) {
        int c = t + i * 256;
        out[(size_t)row * 768 + c] = (x[i] - mu) * rstd * g[c] + bb[c];
    }
}

// ---------------------------------------------------------------------------
extern "C" void kernel_launch(void* const* d_in, const int* in_sizes, int n_in,
                              void* d_out, int out_size)
{
    const float* x1    = (const float*)d_in[0];
    const float* mask1 = (const float*)d_in[1];
    const float* x2    = (const float*)d_in[2];
    const float* mask2 = (const float*)d_in[3];
    const float* q1w = (const float*)d_in[4];  const float* q1b = (const float*)d_in[5];
    const float* k1w = (const float*)d_in[6];  const float* k1b = (const float*)d_in[7];
    const float* v1w = (const float*)d_in[8];  const float* v1b = (const float*)d_in[9];
    const float* q2w = (const float*)d_in[10]; const float* q2b = (const float*)d_in[11];
    const float* k2w = (const float*)d_in[12]; const float* k2b = (const float*)d_in[13];
    const float* v2w = (const float*)d_in[14]; const float* v2b = (const float*)d_in[15];
    const float* d1w = (const float*)d_in[16]; const float* d1b = (const float*)d_in[17];
    const float* d2w = (const float*)d_in[18]; const float* d2b = (const float*)d_in[19];
    const float* ln1g = (const float*)d_in[20]; const float* ln1b = (const float*)d_in[21];
    const float* ln2g = (const float*)d_in[22]; const float* ln2b = (const float*)d_in[23];

    void* sp = nullptr;
    cudaGetSymbolAddress(&sp, g_scratch);
    float* base = (float*)sp;
    float* q1   = base + 0 * MAT;
    float* k1   = base + 1 * MAT;
    float* v1   = base + 2 * MAT;
    float* q2   = base + 3 * MAT;
    float* k2   = base + 4 * MAT;
    float* v2   = base + 5 * MAT;
    float* ctx1 = base + 6 * MAT;
    float* ctx2 = base + 7 * MAT;
    float* t1   = base + 8 * MAT;
    float* t2   = base + 9 * MAT;

    float* out1 = (float*)d_out;
    float* out2 = out1 + MAT;

    dim3 gg(12, 128);  // 768/64 cols x 8192/64 rows
    sgemm_bias_kernel<<<gg, 256>>>(x1, q1w, q1b, q1);
    sgemm_bias_kernel<<<gg, 256>>>(x1, k1w, k1b, k1);
    sgemm_bias_kernel<<<gg, 256>>>(x1, v1w, v1b, v1);
    sgemm_bias_kernel<<<gg, 256>>>(x2, q2w, q2b, q2);
    sgemm_bias_kernel<<<gg, 256>>>(x2, k2w, k2b, k2);
    sgemm_bias_kernel<<<gg, 256>>>(x2, v2w, v2b, v2);

    cudaFuncSetAttribute(flash_attn_kernel,
                         cudaFuncAttributeMaxDynamicSharedMemorySize,
                         FLASH_SMEM_BYTES);
    dim3 fg(S / 64, H, B);
    // ctx1: queries from stream2 attend K1/V1 with mask1
    flash_attn_kernel<<<fg, 256, FLASH_SMEM_BYTES>>>(q2, k1, v1, mask1, ctx1);
    // ctx2: queries from stream1 attend K2/V2 with mask2
    flash_attn_kernel<<<fg, 256, FLASH_SMEM_BYTES>>>(q1, k2, v2, mask2, ctx2);

    sgemm_bias_kernel<<<gg, 256>>>(ctx1, d1w, d1b, t1);
    sgemm_bias_kernel<<<gg, 256>>>(ctx2, d2w, d2b, t2);

    add_ln_kernel<<<M, 256>>>(t1, x1, ln1g, ln1b, out1);
    add_ln_kernel<<<M, 256>>>(t2, x2, ln2g, ln2b, out2);
}

// round 3
// speedup vs baseline: 4.4150x; 4.4129x over previous
#include <cuda_runtime.h>
#include <cstdint>

// ---------------------------------------------------------------------------
// BertBiAttention — round 2: all matmuls on tensor cores via mma.sync tf32.
// B=4, S=2048, HID=768, H=12, HD=64.
// ---------------------------------------------------------------------------

constexpr int B = 4, S = 2048, HID = 768, H = 12, HD = 64;
constexpr int M = B * S;                       // 8192
constexpr size_t MAT = (size_t)M * HID;

__device__ float g_scratch[10 * 6291456];

// round-to-nearest tf32 (keeps value in an f32 register with low bits zeroed)
__device__ __forceinline__ float tf32r(float x) {
    uint32_t u;
    asm("cvt.rna.tf32.f32 %0, %1;" : "=r"(u) : "f"(x));
    return __uint_as_float(u);
}

__device__ __forceinline__ void mma_tf32(float c[4], const uint32_t a[4],
                                         const uint32_t b[2]) {
    asm volatile(
        "mma.sync.aligned.m16n8k8.row.col.f32.tf32.tf32.f32 "
        "{%0,%1,%2,%3}, {%4,%5,%6,%7}, {%8,%9}, {%0,%1,%2,%3};"
        : "+f"(c[0]), "+f"(c[1]), "+f"(c[2]), "+f"(c[3])
        : "r"(a[0]), "r"(a[1]), "r"(a[2]), "r"(a[3]), "r"(b[0]), "r"(b[1]));
}

// ---------------------------------------------------------------------------
// Batched GEMM: C[8192,768] = A @ W + bias, up to 6 problems via blockIdx.z.
// BM=128, BN=64, BK=32. 8 warps in 4(m) x 2(n); warp tile 32x32.
// As stride 36 (=4 mod 32: conflict-free A-frag), Bs stride 72 (=8 mod 32:
// conflict-free B-frag).
// ---------------------------------------------------------------------------
struct GemmBatch {
    const float* A[6]; const float* W[6]; const float* bias[6]; float* C[6];
};

__global__ void __launch_bounds__(256) gemm_tf32_kernel(GemmBatch gb) {
    const int z = blockIdx.z;
    const float* A = gb.A[z];
    const float* W = gb.W[z];
    const float* bias = gb.bias[z];
    float* C = gb.C[z];

    __shared__ float As[128][36];
    __shared__ float Bs[32][72];

    const int tid = threadIdx.x;
    const int warp = tid >> 5, lane = tid & 31;
    const int gq = lane >> 2, tq = lane & 3;
    const int wm = warp & 3, wn = warp >> 2;
    const int row0 = blockIdx.y * 128, col0 = blockIdx.x * 64;

    float acc[2][4][4] = {};

    for (int k0 = 0; k0 < 768; k0 += 32) {
#pragma unroll
        for (int i = 0; i < 4; i++) {
            int idx = tid + i * 256;
            int r = idx >> 3, c4 = (idx & 7) << 2;
            float4 v = *(const float4*)(A + (size_t)(row0 + r) * 768 + k0 + c4);
            *(float4*)&As[r][c4] =
                make_float4(tf32r(v.x), tf32r(v.y), tf32r(v.z), tf32r(v.w));
        }
#pragma unroll
        for (int i = 0; i < 2; i++) {
            int idx = tid + i * 256;
            int r = idx >> 4, c4 = (idx & 15) << 2;
            float4 v = *(const float4*)(W + (size_t)(k0 + r) * 768 + col0 + c4);
            *(float4*)&Bs[r][c4] =
                make_float4(tf32r(v.x), tf32r(v.y), tf32r(v.z), tf32r(v.w));
        }
        __syncthreads();
#pragma unroll
        for (int ks = 0; ks < 4; ks++) {
            int k = ks * 8;
            uint32_t a[2][4];
#pragma unroll
            for (int mi = 0; mi < 2; mi++) {
                int rb = wm * 32 + mi * 16;
                a[mi][0] = __float_as_uint(As[rb + gq][k + tq]);
                a[mi][1] = __float_as_uint(As[rb + 8 + gq][k + tq]);
                a[mi][2] = __float_as_uint(As[rb + gq][k + tq + 4]);
                a[mi][3] = __float_as_uint(As[rb + 8 + gq][k + tq + 4]);
            }
#pragma unroll
            for (int ni = 0; ni < 4; ni++) {
                uint32_t b2[2];
                int cb = wn * 32 + ni * 8 + gq;
                b2[0] = __float_as_uint(Bs[k + tq][cb]);
                b2[1] = __float_as_uint(Bs[k + tq + 4][cb]);
                mma_tf32(acc[0][ni], a[0], b2);
                mma_tf32(acc[1][ni], a[1], b2);
            }
        }
        __syncthreads();
    }

#pragma unroll
    for (int ni = 0; ni < 4; ni++) {
        int col = col0 + wn * 32 + ni * 8 + 2 * tq;
        float2 bv = *(const float2*)(bias + col);
#pragma unroll
        for (int mi = 0; mi < 2; mi++) {
            int rb = row0 + wm * 32 + mi * 16 + gq;
            *(float2*)(C + (size_t)rb * 768 + col) =
                make_float2(acc[mi][ni][0] + bv.x, acc[mi][ni][1] + bv.y);
            *(float2*)(C + (size_t)(rb + 8) * 768 + col) =
                make_float2(acc[mi][ni][2] + bv.x, acc[mi][ni][3] + bv.y);
        }
    }
}

// ---------------------------------------------------------------------------
// Flash attention with tf32 mma. BM=128 (8 warps x 16 rows), BN=64 keys,
// HD=64. Both streams in one launch: blockIdx.z = sel*4 + b.
// Qs/Ps stride 68 (A-frag role), Ks stride 68 (B-frag, col index = key is
// the row of the array -> varies with g -> needs =4 mod 32), Vs stride 72
// (B-frag, row index k+t -> needs =8 mod 32).
// ---------------------------------------------------------------------------
struct FlashArgs {
    const float* Q[2]; const float* K[2]; const float* V[2];
    const float* mask[2]; float* O[2];
};

constexpr int FL_SMEM = (128 * 68 + 64 * 68 + 64 * 72 + 128 * 68) * 4;

__global__ void __launch_bounds__(256) flash_tf32_kernel(FlashArgs fa) {
    extern __shared__ float sm[];
    float* Qs = sm;                      // [128][68]
    float* Ks = Qs + 128 * 68;           // [64][68]
    float* Vs = Ks + 64 * 68;            // [64][72]
    float* Ps = Vs + 64 * 72;            // [128][68]

    const int tid = threadIdx.x;
    const int warp = tid >> 5, lane = tid & 31;
    const int gq = lane >> 2, tq = lane & 3;
    const int sel = blockIdx.z >> 2, b = blockIdx.z & 3;
    const int h = blockIdx.y;
    const int q0 = blockIdx.x * 128;
    const int r0 = warp * 16;

    const float* Q = fa.Q[sel];
    const float* K = fa.K[sel];
    const float* V = fa.V[sel];
    const float* mb = fa.mask[sel] + (size_t)b * S;
    float* O = fa.O[sel];

    const float* Qb = Q + ((size_t)(b * S + q0)) * HID + h * HD;
#pragma unroll
    for (int i = 0; i < 8; i++) {
        int idx = tid + i * 256;
        int r = idx >> 4, c4 = (idx & 15) << 2;
        float4 v = *(const float4*)(Qb + (size_t)r * HID + c4);
        *(float4*)&Qs[r * 68 + c4] =
            make_float4(tf32r(v.x), tf32r(v.y), tf32r(v.z), tf32r(v.w));
    }

    float m_lo = -1e30f, m_hi = -1e30f, l_lo = 0.f, l_hi = 0.f;
    float o[8][4] = {};

    for (int k0 = 0; k0 < S; k0 += 64) {
        __syncthreads();   // prior-iteration K/V reads complete
        const float* Kb = K + ((size_t)(b * S + k0)) * HID + h * HD;
        const float* Vb = V + ((size_t)(b * S + k0)) * HID + h * HD;
#pragma unroll
        for (int i = 0; i < 4; i++) {
            int idx = tid + i * 256;
            int r = idx >> 4, c4 = (idx & 15) << 2;
            float4 kv = *(const float4*)(Kb + (size_t)r * HID + c4);
            *(float4*)&Ks[r * 68 + c4] =
                make_float4(tf32r(kv.x), tf32r(kv.y), tf32r(kv.z), tf32r(kv.w));
            float4 vv = *(const float4*)(Vb + (size_t)r * HID + c4);
            *(float4*)&Vs[r * 72 + c4] =
                make_float4(tf32r(vv.x), tf32r(vv.y), tf32r(vv.z), tf32r(vv.w));
        }
        __syncthreads();

        // S = Q K^T
        float s[8][4] = {};
#pragma unroll
        for (int ks = 0; ks < 8; ks++) {
            int k = ks * 8;
            uint32_t a[4];
            a[0] = __float_as_uint(Qs[(r0 + gq) * 68 + k + tq]);
            a[1] = __float_as_uint(Qs[(r0 + 8 + gq) * 68 + k + tq]);
            a[2] = __float_as_uint(Qs[(r0 + gq) * 68 + k + tq + 4]);
            a[3] = __float_as_uint(Qs[(r0 + 8 + gq) * 68 + k + tq + 4]);
#pragma unroll
            for (int nf = 0; nf < 8; nf++) {
                uint32_t b2[2];
                b2[0] = __float_as_uint(Ks[(nf * 8 + gq) * 68 + k + tq]);
                b2[1] = __float_as_uint(Ks[(nf * 8 + gq) * 68 + k + tq + 4]);
                mma_tf32(s[nf], a, b2);
            }
        }

        // online softmax (rows r0+gq and r0+8+gq)
        float mloc_lo = -1e30f, mloc_hi = -1e30f;
#pragma unroll
        for (int nf = 0; nf < 8; nf++) {
            float2 mv = *(const float2*)(mb + k0 + nf * 8 + 2 * tq);
            s[nf][0] = s[nf][0] * 0.125f + mv.x;
            s[nf][1] = s[nf][1] * 0.125f + mv.y;
            s[nf][2] = s[nf][2] * 0.125f + mv.x;
            s[nf][3] = s[nf][3] * 0.125f + mv.y;
            mloc_lo = fmaxf(mloc_lo, fmaxf(s[nf][0], s[nf][1]));
            mloc_hi = fmaxf(mloc_hi, fmaxf(s[nf][2], s[nf][3]));
        }
        mloc_lo = fmaxf(mloc_lo, __shfl_xor_sync(0xffffffffu, mloc_lo, 1));
        mloc_lo = fmaxf(mloc_lo, __shfl_xor_sync(0xffffffffu, mloc_lo, 2));
        mloc_hi = fmaxf(mloc_hi, __shfl_xor_sync(0xffffffffu, mloc_hi, 1));
        mloc_hi = fmaxf(mloc_hi, __shfl_xor_sync(0xffffffffu, mloc_hi, 2));
        float mn_lo = fmaxf(m_lo, mloc_lo), mn_hi = fmaxf(m_hi, mloc_hi);
        float al_lo = __expf(m_lo - mn_lo), al_hi = __expf(m_hi - mn_hi);

        float ls_lo = 0.f, ls_hi = 0.f;
#pragma unroll
        for (int nf = 0; nf < 8; nf++) {
            float p0 = __expf(s[nf][0] - mn_lo);
            float p1 = __expf(s[nf][1] - mn_lo);
            float p2 = __expf(s[nf][2] - mn_hi);
            float p3 = __expf(s[nf][3] - mn_hi);
            ls_lo += p0 + p1;
            ls_hi += p2 + p3;
            *(float2*)&Ps[(r0 + gq) * 68 + nf * 8 + 2 * tq] =
                make_float2(tf32r(p0), tf32r(p1));
            *(float2*)&Ps[(r0 + 8 + gq) * 68 + nf * 8 + 2 * tq] =
                make_float2(tf32r(p2), tf32r(p3));
        }
        ls_lo += __shfl_xor_sync(0xffffffffu, ls_lo, 1);
        ls_lo += __shfl_xor_sync(0xffffffffu, ls_lo, 2);
        ls_hi += __shfl_xor_sync(0xffffffffu, ls_hi, 1);
        ls_hi += __shfl_xor_sync(0xffffffffu, ls_hi, 2);
        l_lo = l_lo * al_lo + ls_lo;
        l_hi = l_hi * al_hi + ls_hi;
        m_lo = mn_lo;
        m_hi = mn_hi;
#pragma unroll
        for (int nf = 0; nf < 8; nf++) {
            o[nf][0] *= al_lo; o[nf][1] *= al_lo;
            o[nf][2] *= al_hi; o[nf][3] *= al_hi;
        }
        __syncwarp();   // P written by this warp (its own 16 rows only)

        // O += P V
#pragma unroll
        for (int ks = 0; ks < 8; ks++) {
            int k = ks * 8;
            uint32_t a[4];
            a[0] = __float_as_uint(Ps[(r0 + gq) * 68 + k + tq]);
            a[1] = __float_as_uint(Ps[(r0 + 8 + gq) * 68 + k + tq]);
            a[2] = __float_as_uint(Ps[(r0 + gq) * 68 + k + tq + 4]);
            a[3] = __float_as_uint(Ps[(r0 + 8 + gq) * 68 + k + tq + 4]);
#pragma unroll
            for (int nf = 0; nf < 8; nf++) {
                uint32_t b2[2];
                b2[0] = __float_as_uint(Vs[(k + tq) * 72 + nf * 8 + gq]);
                b2[1] = __float_as_uint(Vs[(k + tq + 4) * 72 + nf * 8 + gq]);
                mma_tf32(o[nf], a, b2);
            }
        }
    }

    float inv_lo = 1.f / l_lo, inv_hi = 1.f / l_hi;
    float* Ob = O + ((size_t)(b * S + q0)) * HID + h * HD;
#pragma unroll
    for (int nf = 0; nf < 8; nf++) {
        int col = nf * 8 + 2 * tq;
        *(float2*)(Ob + (size_t)(r0 + gq) * HID + col) =
            make_float2(o[nf][0] * inv_lo, o[nf][1] * inv_lo);
        *(float2*)(Ob + (size_t)(r0 + 8 + gq) * HID + col) =
            make_float2(o[nf][2] * inv_hi, o[nf][3] * inv_hi);
    }
}

// ---------------------------------------------------------------------------
// out = LayerNorm(T + residual) * g + b, both streams via blockIdx.y
// ---------------------------------------------------------------------------
__global__ void __launch_bounds__(256) add_ln_kernel(
    const float* __restrict__ T1, const float* __restrict__ R1,
    const float* __restrict__ g1, const float* __restrict__ b1,
    float* __restrict__ o1,
    const float* __restrict__ T2, const float* __restrict__ R2,
    const float* __restrict__ g2, const float* __restrict__ b2,
    float* __restrict__ o2)
{
    const int st = blockIdx.y;
    const float* T = st ? T2 : T1;
    const float* R = st ? R2 : R1;
    const float* g = st ? g2 : g1;
    const float* bb = st ? b2 : b1;
    float* out = st ? o2 : o1;

    const int row = blockIdx.x;
    const int t = threadIdx.x;
    const float* Tr = T + (size_t)row * 768;
    const float* Rr = R + (size_t)row * 768;

    float x[3];
    float sum = 0.f, sq = 0.f;
#pragma unroll
    for (int i = 0; i < 3; i++) {
        int c = t + i * 256;
        x[i] = Tr[c] + Rr[c];
        sum += x[i];
        sq += x[i] * x[i];
    }

    __shared__ float sa[8], sb[8];
#pragma unroll
    for (int off = 16; off; off >>= 1) {
        sum += __shfl_down_sync(0xffffffffu, sum, off);
        sq  += __shfl_down_sync(0xffffffffu, sq,  off);
    }
    int w = t >> 5, lane = t & 31;
    if (lane == 0) { sa[w] = sum; sb[w] = sq; }
    __syncthreads();
    if (t < 32) {
        sum = (t < 8) ? sa[t] : 0.f;
        sq  = (t < 8) ? sb[t] : 0.f;
#pragma unroll
        for (int off = 4; off; off >>= 1) {
            sum += __shfl_down_sync(0xffffffffu, sum, off);
            sq  += __shfl_down_sync(0xffffffffu, sq,  off);
        }
        if (t == 0) { sa[0] = sum; sb[0] = sq; }
    }
    __syncthreads();
    sum = sa[0]; sq = sb[0];

    float mu  = sum * (1.f / 768.f);
    float var = sq * (1.f / 768.f) - mu * mu;
    float rstd = rsqrtf(var + 1e-12f);
#pragma unroll
    for (int i = 0; i < 3; i++) {
        int c = t + i * 256;
        out[(size_t)row * 768 + c] = (x[i] - mu) * rstd * g[c] + bb[c];
    }
}

// ---------------------------------------------------------------------------
extern "C" void kernel_launch(void* const* d_in, const int* in_sizes, int n_in,
                              void* d_out, int out_size)
{
    const float* x1    = (const float*)d_in[0];
    const float* mask1 = (const float*)d_in[1];
    const float* x2    = (const float*)d_in[2];
    const float* mask2 = (const float*)d_in[3];
    const float* q1w = (const float*)d_in[4];  const float* q1b = (const float*)d_in[5];
    const float* k1w = (const float*)d_in[6];  const float* k1b = (const float*)d_in[7];
    const float* v1w = (const float*)d_in[8];  const float* v1b = (const float*)d_in[9];
    const float* q2w = (const float*)d_in[10]; const float* q2b = (const float*)d_in[11];
    const float* k2w = (const float*)d_in[12]; const float* k2b = (const float*)d_in[13];
    const float* v2w = (const float*)d_in[14]; const float* v2b = (const float*)d_in[15];
    const float* d1w = (const float*)d_in[16]; const float* d1b = (const float*)d_in[17];
    const float* d2w = (const float*)d_in[18]; const float* d2b = (const float*)d_in[19];
    const float* ln1g = (const float*)d_in[20]; const float* ln1b = (const float*)d_in[21];
    const float* ln2g = (const float*)d_in[22]; const float* ln2b = (const float*)d_in[23];

    void* sp = nullptr;
    cudaGetSymbolAddress(&sp, g_scratch);
    float* base = (float*)sp;
    float* q1   = base + 0 * MAT;
    float* k1   = base + 1 * MAT;
    float* v1   = base + 2 * MAT;
    float* q2   = base + 3 * MAT;
    float* k2   = base + 4 * MAT;
    float* v2   = base + 5 * MAT;
    float* ctx1 = base + 6 * MAT;
    float* ctx2 = base + 7 * MAT;
    float* t1   = base + 8 * MAT;
    float* t2   = base + 9 * MAT;

    float* out1 = (float*)d_out;
    float* out2 = out1 + MAT;

    // 6 input projections in one launch
    GemmBatch proj;
    proj.A[0] = x1; proj.W[0] = q1w; proj.bias[0] = q1b; proj.C[0] = q1;
    proj.A[1] = x1; proj.W[1] = k1w; proj.bias[1] = k1b; proj.C[1] = k1;
    proj.A[2] = x1; proj.W[2] = v1w; proj.bias[2] = v1b; proj.C[2] = v1;
    proj.A[3] = x2; proj.W[3] = q2w; proj.bias[3] = q2b; proj.C[3] = q2;
    proj.A[4] = x2; proj.W[4] = k2w; proj.bias[4] = k2b; proj.C[4] = k2;
    proj.A[5] = x2; proj.W[5] = v2w; proj.bias[5] = v2b; proj.C[5] = v2;
    gemm_tf32_kernel<<<dim3(12, 64, 6), 256>>>(proj);

    // both attention streams in one launch
    cudaFuncSetAttribute(flash_tf32_kernel,
                         cudaFuncAttributeMaxDynamicSharedMemorySize, FL_SMEM);
    FlashArgs fa;
    fa.Q[0] = q2; fa.K[0] = k1; fa.V[0] = v1; fa.mask[0] = mask1; fa.O[0] = ctx1;
    fa.Q[1] = q1; fa.K[1] = k2; fa.V[1] = v2; fa.mask[1] = mask2; fa.O[1] = ctx2;
    flash_tf32_kernel<<<dim3(S / 128, H, 8), 256, FL_SMEM>>>(fa);

    // 2 output projections in one launch
    GemmBatch dp;
    dp.A[0] = ctx1; dp.W[0] = d1w; dp.bias[0] = d1b; dp.C[0] = t1;
    dp.A[1] = ctx2; dp.W[1] = d2w; dp.bias[1] = d2b; dp.C[1] = t2;
    for (int i = 2; i < 6; i++) { dp.A[i] = nullptr; dp.W[i] = nullptr; dp.bias[i] = nullptr; dp.C[i] = nullptr; }
    gemm_tf32_kernel<<<dim3(12, 64, 2), 256>>>(dp);

    add_ln_kernel<<<dim3(M, 2), 256>>>(t1, x1, ln1g, ln1b, out1,
                                       t2, x2, ln2g, ln2b, out2);
}

// round 4
// speedup vs baseline: 6.2985x; 1.4266x over previous
#include <cuda_runtime.h>
#include <cstdint>

// ---------------------------------------------------------------------------
// BertBiAttention — round 3: cp.async double-buffered tf32 mma pipelines.
// B=4, S=2048, HID=768, H=12, HD=64.
// ---------------------------------------------------------------------------

constexpr int B = 4, S = 2048, HID = 768, H = 12, HD = 64;
constexpr int M = B * S;                       // 8192
constexpr size_t MAT = (size_t)M * HID;

__device__ float g_scratch[10 * 6291456];

__device__ __forceinline__ void cp16(void* dst_smem, const void* src) {
    uint32_t d = (uint32_t)__cvta_generic_to_shared(dst_smem);
    asm volatile("cp.async.cg.shared.global [%0], [%1], 16;" :: "r"(d), "l"(src));
}
__device__ __forceinline__ void cp_commit() {
    asm volatile("cp.async.commit_group;");
}
__device__ __forceinline__ void cp_wait0() {
    asm volatile("cp.async.wait_group 0;");
}

// mma.sync m16n8k8 tf32: raw f32 bits in, HW truncates mantissa to tf32.
__device__ __forceinline__ void mma_tf32(float c[4], const float a[4],
                                         const float b2[2]) {
    asm volatile(
        "mma.sync.aligned.m16n8k8.row.col.f32.tf32.tf32.f32 "
        "{%0,%1,%2,%3}, {%4,%5,%6,%7}, {%8,%9}, {%0,%1,%2,%3};"
        : "+f"(c[0]), "+f"(c[1]), "+f"(c[2]), "+f"(c[3])
        : "r"(__float_as_uint(a[0])), "r"(__float_as_uint(a[1])),
          "r"(__float_as_uint(a[2])), "r"(__float_as_uint(a[3])),
          "r"(__float_as_uint(b2[0])), "r"(__float_as_uint(b2[1])));
}

// ---------------------------------------------------------------------------
// Batched GEMM: C[8192,768] = A @ W + bias. BM=128, BN=64, BK=32, 8 warps
// (4m x 2n), warp tile 32x32, double-buffered cp.async.
// As stride 36 (=4 mod 32), Bs stride 72 (=8 mod 32): conflict-free frags.
// ---------------------------------------------------------------------------
struct GemmBatch {
    const float* A[6]; const float* W[6]; const float* bias[6]; float* C[6];
};

constexpr int GEMM_SMEM = (2 * 128 * 36 + 2 * 32 * 72) * 4;  // 55296

__global__ void __launch_bounds__(256) gemm_tf32_kernel(GemmBatch gb) {
    const int z = blockIdx.z;
    const float* A = gb.A[z];
    const float* W = gb.W[z];
    const float* bias = gb.bias[z];
    float* C = gb.C[z];

    extern __shared__ float smg[];
    float* As = smg;                 // [2][128][36]
    float* Bs = smg + 2 * 128 * 36;  // [2][32][72]

    const int tid = threadIdx.x;
    const int warp = tid >> 5, lane = tid & 31;
    const int gq = lane >> 2, tq = lane & 3;
    const int wm = warp & 3, wn = warp >> 2;
    const int row0 = blockIdx.y * 128, col0 = blockIdx.x * 64;

    // load mappings
    const int ar = tid >> 3, ac = (tid & 7) << 2;    // +i*32 rows
    const int br = tid >> 4, bc = (tid & 15) << 2;   // +i*16 rows

    auto load_tile = [&](int st, int k0) {
        float* Ab = As + st * 128 * 36;
        float* Bb = Bs + st * 32 * 72;
#pragma unroll
        for (int i = 0; i < 4; i++) {
            int r = ar + i * 32;
            cp16(&Ab[r * 36 + ac], A + (size_t)(row0 + r) * 768 + k0 + ac);
        }
#pragma unroll
        for (int i = 0; i < 2; i++) {
            int r = br + i * 16;
            cp16(&Bb[r * 72 + bc], W + (size_t)(k0 + r) * 768 + col0 + bc);
        }
    };

    float acc[2][4][4] = {};

    load_tile(0, 0);
    cp_commit();

    for (int kt = 0; kt < 24; kt++) {
        cp_wait0();
        __syncthreads();
        if (kt + 1 < 24) {
            load_tile((kt + 1) & 1, (kt + 1) * 32);
            cp_commit();
        }
        const float* Ab = As + (kt & 1) * 128 * 36;
        const float* Bb = Bs + (kt & 1) * 32 * 72;
#pragma unroll
        for (int ks = 0; ks < 4; ks++) {
            int k = ks * 8;
            float a[2][4];
#pragma unroll
            for (int mi = 0; mi < 2; mi++) {
                int rb = wm * 32 + mi * 16;
                a[mi][0] = Ab[(rb + gq) * 36 + k + tq];
                a[mi][1] = Ab[(rb + 8 + gq) * 36 + k + tq];
                a[mi][2] = Ab[(rb + gq) * 36 + k + tq + 4];
                a[mi][3] = Ab[(rb + 8 + gq) * 36 + k + tq + 4];
            }
#pragma unroll
            for (int ni = 0; ni < 4; ni++) {
                int cb = wn * 32 + ni * 8 + gq;
                float b2[2];
                b2[0] = Bb[(k + tq) * 72 + cb];
                b2[1] = Bb[(k + tq + 4) * 72 + cb];
                mma_tf32(acc[0][ni], a[0], b2);
                mma_tf32(acc[1][ni], a[1], b2);
            }
        }
    }

#pragma unroll
    for (int ni = 0; ni < 4; ni++) {
        int col = col0 + wn * 32 + ni * 8 + 2 * tq;
        float2 bv = *(const float2*)(bias + col);
#pragma unroll
        for (int mi = 0; mi < 2; mi++) {
            int rb = row0 + wm * 32 + mi * 16 + gq;
            *(float2*)(C + (size_t)rb * 768 + col) =
                make_float2(acc[mi][ni][0] + bv.x, acc[mi][ni][1] + bv.y);
            *(float2*)(C + (size_t)(rb + 8) * 768 + col) =
                make_float2(acc[mi][ni][2] + bv.x, acc[mi][ni][3] + bv.y);
        }
    }
}

// ---------------------------------------------------------------------------
// Flash attention, tf32 mma, double-buffered K/V via cp.async, Q fragments
// register-resident. BM=128 (8 warps x 16 rows), BN=64 keys, HD=64.
// blockIdx.z = sel*4 + b covers both streams.
// ---------------------------------------------------------------------------
struct FlashArgs {
    const float* Q[2]; const float* K[2]; const float* V[2];
    const float* mask[2]; float* O[2];
};

constexpr int FL_SMEM = (2 * 64 * 68 + 2 * 64 * 72 + 128 * 68) * 4;  // 106496

__global__ void __launch_bounds__(256) flash_tf32_kernel(FlashArgs fa) {
    extern __shared__ float sm[];
    float* Ks = sm;                    // [2][64][68]
    float* Vs = sm + 2 * 64 * 68;      // [2][64][72]
    float* Ps = Vs + 2 * 64 * 72;      // [128][68]

    const int tid = threadIdx.x;
    const int warp = tid >> 5, lane = tid & 31;
    const int gq = lane >> 2, tq = lane & 3;
    const int sel = blockIdx.z >> 2, b = blockIdx.z & 3;
    const int h = blockIdx.y;
    const int q0 = blockIdx.x * 128;
    const int r0 = warp * 16;

    const float* K = fa.K[sel];
    const float* V = fa.V[sel];
    const float* mb = fa.mask[sel] + (size_t)b * S;
    float* O = fa.O[sel];

    const float* Kbase = K + ((size_t)(b * S)) * HID + h * HD;
    const float* Vbase = V + ((size_t)(b * S)) * HID + h * HD;

    const int lr = tid >> 4, lc = (tid & 15) << 2;   // K/V load mapping (+i*16 rows)

    auto load_kv = [&](int st, int k0) {
        float* Kb = Ks + st * 64 * 68;
        float* Vb = Vs + st * 64 * 72;
        const float* Kg = Kbase + (size_t)k0 * HID;
        const float* Vg = Vbase + (size_t)k0 * HID;
#pragma unroll
        for (int i = 0; i < 4; i++) {
            int r = lr + i * 16;
            cp16(&Kb[r * 68 + lc], Kg + (size_t)r * HID + lc);
            cp16(&Vb[r * 72 + lc], Vg + (size_t)r * HID + lc);
        }
    };

    // Q fragments: register-resident for the whole kernel.
    float qf[8][4];
    {
        const float* Qb = fa.Q[sel] + ((size_t)(b * S + q0 + r0)) * HID + h * HD;
#pragma unroll
        for (int ks = 0; ks < 8; ks++) {
            int k = ks * 8;
            qf[ks][0] = Qb[(size_t)gq * HID + k + tq];
            qf[ks][1] = Qb[(size_t)(8 + gq) * HID + k + tq];
            qf[ks][2] = Qb[(size_t)gq * HID + k + tq + 4];
            qf[ks][3] = Qb[(size_t)(8 + gq) * HID + k + tq + 4];
        }
    }

    float m_lo = -1e30f, m_hi = -1e30f, l_lo = 0.f, l_hi = 0.f;
    float o[8][4] = {};

    load_kv(0, 0);
    cp_commit();

    constexpr int NIT = S / 64;
    for (int it = 0; it < NIT; it++) {
        cp_wait0();
        __syncthreads();
        if (it + 1 < NIT) {
            load_kv((it + 1) & 1, (it + 1) * 64);
            cp_commit();
        }
        const float* Kb = Ks + (it & 1) * 64 * 68;
        const float* Vb = Vs + (it & 1) * 64 * 72;
        const int k0 = it * 64;

        // S = Q K^T
        float s[8][4] = {};
#pragma unroll
        for (int ks = 0; ks < 8; ks++) {
            int k = ks * 8;
#pragma unroll
            for (int nf = 0; nf < 8; nf++) {
                float b2[2];
                b2[0] = Kb[(nf * 8 + gq) * 68 + k + tq];
                b2[1] = Kb[(nf * 8 + gq) * 68 + k + tq + 4];
                mma_tf32(s[nf], qf[ks], b2);
            }
        }

        // online softmax
        float mloc_lo = -1e30f, mloc_hi = -1e30f;
#pragma unroll
        for (int nf = 0; nf < 8; nf++) {
            float2 mv = *(const float2*)(mb + k0 + nf * 8 + 2 * tq);
            s[nf][0] = s[nf][0] * 0.125f + mv.x;
            s[nf][1] = s[nf][1] * 0.125f + mv.y;
            s[nf][2] = s[nf][2] * 0.125f + mv.x;
            s[nf][3] = s[nf][3] * 0.125f + mv.y;
            mloc_lo = fmaxf(mloc_lo, fmaxf(s[nf][0], s[nf][1]));
            mloc_hi = fmaxf(mloc_hi, fmaxf(s[nf][2], s[nf][3]));
        }
        mloc_lo = fmaxf(mloc_lo, __shfl_xor_sync(0xffffffffu, mloc_lo, 1));
        mloc_lo = fmaxf(mloc_lo, __shfl_xor_sync(0xffffffffu, mloc_lo, 2));
        mloc_hi = fmaxf(mloc_hi, __shfl_xor_sync(0xffffffffu, mloc_hi, 1));
        mloc_hi = fmaxf(mloc_hi, __shfl_xor_sync(0xffffffffu, mloc_hi, 2));
        float mn_lo = fmaxf(m_lo, mloc_lo), mn_hi = fmaxf(m_hi, mloc_hi);
        float al_lo = __expf(m_lo - mn_lo), al_hi = __expf(m_hi - mn_hi);

        float ls_lo = 0.f, ls_hi = 0.f;
#pragma unroll
        for (int nf = 0; nf < 8; nf++) {
            float p0 = __expf(s[nf][0] - mn_lo);
            float p1 = __expf(s[nf][1] - mn_lo);
            float p2 = __expf(s[nf][2] - mn_hi);
            float p3 = __expf(s[nf][3] - mn_hi);
            ls_lo += p0 + p1;
            ls_hi += p2 + p3;
            *(float2*)&Ps[(r0 + gq) * 68 + nf * 8 + 2 * tq] = make_float2(p0, p1);
            *(float2*)&Ps[(r0 + 8 + gq) * 68 + nf * 8 + 2 * tq] = make_float2(p2, p3);
        }
        ls_lo += __shfl_xor_sync(0xffffffffu, ls_lo, 1);
        ls_lo += __shfl_xor_sync(0xffffffffu, ls_lo, 2);
        ls_hi += __shfl_xor_sync(0xffffffffu, ls_hi, 1);
        ls_hi += __shfl_xor_sync(0xffffffffu, ls_hi, 2);
        l_lo = l_lo * al_lo + ls_lo;
        l_hi = l_hi * al_hi + ls_hi;
        m_lo = mn_lo;
        m_hi = mn_hi;
#pragma unroll
        for (int nf = 0; nf < 8; nf++) {
            o[nf][0] *= al_lo; o[nf][1] *= al_lo;
            o[nf][2] *= al_hi; o[nf][3] *= al_hi;
        }
        __syncwarp();   // P rows owned by this warp only

        // O += P V
#pragma unroll
        for (int ks = 0; ks < 8; ks++) {
            int k = ks * 8;
            float a[4];
            a[0] = Ps[(r0 + gq) * 68 + k + tq];
            a[1] = Ps[(r0 + 8 + gq) * 68 + k + tq];
            a[2] = Ps[(r0 + gq) * 68 + k + tq + 4];
            a[3] = Ps[(r0 + 8 + gq) * 68 + k + tq + 4];
#pragma unroll
            for (int nf = 0; nf < 8; nf++) {
                float b2[2];
                b2[0] = Vb[(k + tq) * 72 + nf * 8 + gq];
                b2[1] = Vb[(k + tq + 4) * 72 + nf * 8 + gq];
                mma_tf32(o[nf], a, b2);
            }
        }
    }

    float inv_lo = 1.f / l_lo, inv_hi = 1.f / l_hi;
    float* Ob = O + ((size_t)(b * S + q0)) * HID + h * HD;
#pragma unroll
    for (int nf = 0; nf < 8; nf++) {
        int col = nf * 8 + 2 * tq;
        *(float2*)(Ob + (size_t)(r0 + gq) * HID + col) =
            make_float2(o[nf][0] * inv_lo, o[nf][1] * inv_lo);
        *(float2*)(Ob + (size_t)(r0 + 8 + gq) * HID + col) =
            make_float2(o[nf][2] * inv_hi, o[nf][3] * inv_hi);
    }
}

// ---------------------------------------------------------------------------
// out = LayerNorm(T + residual) * g + b. Warp per row, float4, no smem.
// grid = (M/8, 2); 8 warps/block.
// ---------------------------------------------------------------------------
__global__ void __launch_bounds__(256) add_ln_kernel(
    const float* __restrict__ T1, const float* __restrict__ R1,
    const float* __restrict__ g1, const float* __restrict__ b1,
    float* __restrict__ o1,
    const float* __restrict__ T2, const float* __restrict__ R2,
    const float* __restrict__ g2, const float* __restrict__ b2,
    float* __restrict__ o2)
{
    const int st = blockIdx.y;
    const float* T = st ? T2 : T1;
    const float* R = st ? R2 : R1;
    const float* g = st ? g2 : g1;
    const float* bb = st ? b2 : b1;
    float* out = st ? o2 : o1;

    const int warp = threadIdx.x >> 5, lane = threadIdx.x & 31;
    const int row = blockIdx.x * 8 + warp;
    const float* Tr = T + (size_t)row * 768;
    const float* Rr = R + (size_t)row * 768;

    float4 x[6];
    float sum = 0.f, sq = 0.f;
#pragma unroll
    for (int j = 0; j < 6; j++) {
        int c = (j * 32 + lane) * 4;
        float4 t = *(const float4*)(Tr + c);
        float4 r = *(const float4*)(Rr + c);
        x[j] = make_float4(t.x + r.x, t.y + r.y, t.z + r.z, t.w + r.w);
        sum += x[j].x + x[j].y + x[j].z + x[j].w;
        sq += x[j].x * x[j].x + x[j].y * x[j].y +
              x[j].z * x[j].z + x[j].w * x[j].w;
    }
#pragma unroll
    for (int off = 16; off; off >>= 1) {
        sum += __shfl_xor_sync(0xffffffffu, sum, off);
        sq  += __shfl_xor_sync(0xffffffffu, sq,  off);
    }
    float mu = sum * (1.f / 768.f);
    float var = sq * (1.f / 768.f) - mu * mu;
    float rstd = rsqrtf(var + 1e-12f);
#pragma unroll
    for (int j = 0; j < 6; j++) {
        int c = (j * 32 + lane) * 4;
        float4 gv = *(const float4*)(g + c);
        float4 bv = *(const float4*)(bb + c);
        float4 ov;
        ov.x = (x[j].x - mu) * rstd * gv.x + bv.x;
        ov.y = (x[j].y - mu) * rstd * gv.y + bv.y;
        ov.z = (x[j].z - mu) * rstd * gv.z + bv.z;
        ov.w = (x[j].w - mu) * rstd * gv.w + bv.w;
        *(float4*)(out + (size_t)row * 768 + c) = ov;
    }
}

// ---------------------------------------------------------------------------
extern "C" void kernel_launch(void* const* d_in, const int* in_sizes, int n_in,
                              void* d_out, int out_size)
{
    const float* x1    = (const float*)d_in[0];
    const float* mask1 = (const float*)d_in[1];
    const float* x2    = (const float*)d_in[2];
    const float* mask2 = (const float*)d_in[3];
    const float* q1w = (const float*)d_in[4];  const float* q1b = (const float*)d_in[5];
    const float* k1w = (const float*)d_in[6];  const float* k1b = (const float*)d_in[7];
    const float* v1w = (const float*)d_in[8];  const float* v1b = (const float*)d_in[9];
    const float* q2w = (const float*)d_in[10]; const float* q2b = (const float*)d_in[11];
    const float* k2w = (const float*)d_in[12]; const float* k2b = (const float*)d_in[13];
    const float* v2w = (const float*)d_in[14]; const float* v2b = (const float*)d_in[15];
    const float* d1w = (const float*)d_in[16]; const float* d1b = (const float*)d_in[17];
    const float* d2w = (const float*)d_in[18]; const float* d2b = (const float*)d_in[19];
    const float* ln1g = (const float*)d_in[20]; const float* ln1b = (const float*)d_in[21];
    const float* ln2g = (const float*)d_in[22]; const float* ln2b = (const float*)d_in[23];

    void* sp = nullptr;
    cudaGetSymbolAddress(&sp, g_scratch);
    float* base = (float*)sp;
    float* q1   = base + 0 * MAT;
    float* k1   = base + 1 * MAT;
    float* v1   = base + 2 * MAT;
    float* q2   = base + 3 * MAT;
    float* k2   = base + 4 * MAT;
    float* v2   = base + 5 * MAT;
    float* ctx1 = base + 6 * MAT;
    float* ctx2 = base + 7 * MAT;
    float* t1   = base + 8 * MAT;
    float* t2   = base + 9 * MAT;

    float* out1 = (float*)d_out;
    float* out2 = out1 + MAT;

    cudaFuncSetAttribute(gemm_tf32_kernel,
                         cudaFuncAttributeMaxDynamicSharedMemorySize, GEMM_SMEM);
    cudaFuncSetAttribute(flash_tf32_kernel,
                         cudaFuncAttributeMaxDynamicSharedMemorySize, FL_SMEM);

    // 6 input projections in one launch
    GemmBatch proj;
    proj.A[0] = x1; proj.W[0] = q1w; proj.bias[0] = q1b; proj.C[0] = q1;
    proj.A[1] = x1; proj.W[1] = k1w; proj.bias[1] = k1b; proj.C[1] = k1;
    proj.A[2] = x1; proj.W[2] = v1w; proj.bias[2] = v1b; proj.C[2] = v1;
    proj.A[3] = x2; proj.W[3] = q2w; proj.bias[3] = q2b; proj.C[3] = q2;
    proj.A[4] = x2; proj.W[4] = k2w; proj.bias[4] = k2b; proj.C[4] = k2;
    proj.A[5] = x2; proj.W[5] = v2w; proj.bias[5] = v2b; proj.C[5] = v2;
    gemm_tf32_kernel<<<dim3(12, 64, 6), 256, GEMM_SMEM>>>(proj);

    // both attention streams in one launch
    FlashArgs fa;
    fa.Q[0] = q2; fa.K[0] = k1; fa.V[0] = v1; fa.mask[0] = mask1; fa.O[0] = ctx1;
    fa.Q[1] = q1; fa.K[1] = k2; fa.V[1] = v2; fa.mask[1] = mask2; fa.O[1] = ctx2;
    flash_tf32_kernel<<<dim3(S / 128, H, 8), 256, FL_SMEM>>>(fa);

    // 2 output projections in one launch
    GemmBatch dp;
    dp.A[0] = ctx1; dp.W[0] = d1w; dp.bias[0] = d1b; dp.C[0] = t1;
    dp.A[1] = ctx2; dp.W[1] = d2w; dp.bias[1] = d2b; dp.C[1] = t2;
    for (int i = 2; i < 6; i++) {
        dp.A[i] = nullptr; dp.W[i] = nullptr; dp.bias[i] = nullptr; dp.C[i] = nullptr;
    }
    gemm_tf32_kernel<<<dim3(12, 64, 2), 256, GEMM_SMEM>>>(dp);

    add_ln_kernel<<<dim3(M / 8, 2), 256>>>(t1, x1, ln1g, ln1b, out1,
                                           t2, x2, ln2g, ln2b, out2);
}

// round 5
// speedup vs baseline: 9.6582x; 1.5334x over previous
#include <cuda_runtime.h>
#include <cuda_bf16.h>
#include <cstdint>

// ---------------------------------------------------------------------------
// BertBiAttention — round 4: bf16 m16n8k16 mma everywhere, P in registers.
// B=4, S=2048, HID=768, H=12, HD=64.
// ---------------------------------------------------------------------------

constexpr int B = 4, S = 2048, HID = 768, H = 12, HD = 64;
constexpr int M = B * S;                       // 8192
constexpr size_t MAT = (size_t)M * HID;        // 6.29M elems

__device__ float g_scratch[10 * 6291456];

using bf16 = __nv_bfloat16;

__device__ __forceinline__ void cp16(void* dst_smem, const void* src) {
    uint32_t d = (uint32_t)__cvta_generic_to_shared(dst_smem);
    asm volatile("cp.async.cg.shared.global [%0], [%1], 16;" :: "r"(d), "l"(src));
}
__device__ __forceinline__ void cp_commit() { asm volatile("cp.async.commit_group;"); }
__device__ __forceinline__ void cp_wait0()  { asm volatile("cp.async.wait_group 0;"); }

__device__ __forceinline__ void mma_bf16(float c[4], const uint32_t a[4],
                                         uint32_t b0, uint32_t b1) {
    asm volatile(
        "mma.sync.aligned.m16n8k16.row.col.f32.bf16.bf16.f32 "
        "{%0,%1,%2,%3}, {%4,%5,%6,%7}, {%8,%9}, {%0,%1,%2,%3};"
        : "+f"(c[0]), "+f"(c[1]), "+f"(c[2]), "+f"(c[3])
        : "r"(a[0]), "r"(a[1]), "r"(a[2]), "r"(a[3]), "r"(b0), "r"(b1));
}

// pack: lo -> bits[0:16), hi -> bits[16:32)
__device__ __forceinline__ uint32_t bf16pack(float hi, float lo) {
    uint32_t r;
    asm("cvt.rn.bf16x2.f32 %0, %1, %2;" : "=r"(r) : "f"(hi), "f"(lo));
    return r;
}

__device__ __forceinline__ void ldsm_x2_trans(uint32_t& r0, uint32_t& r1,
                                              uint32_t smem_addr) {
    asm volatile("ldmatrix.sync.aligned.m8n8.x2.trans.shared.b16 {%0,%1}, [%2];"
                 : "=r"(r0), "=r"(r1) : "r"(smem_addr));
}

// ---------------------------------------------------------------------------
// Converters
// ---------------------------------------------------------------------------
__global__ void __launch_bounds__(256) conv_x_kernel(
    const float* __restrict__ x1, const float* __restrict__ x2,
    bf16* __restrict__ o1, bf16* __restrict__ o2)
{
    const float* x = blockIdx.y ? x2 : x1;
    bf16* o = blockIdx.y ? o2 : o1;
    const int n4 = (int)(MAT / 4);
    for (int i = blockIdx.x * 256 + threadIdx.x; i < n4; i += gridDim.x * 256) {
        float4 v = *(const float4*)(x + (size_t)i * 4);
        uint32_t lo = bf16pack(v.y, v.x);
        uint32_t hi = bf16pack(v.w, v.z);
        *(uint2*)(o + (size_t)i * 4) = make_uint2(lo, hi);
    }
}

struct WPtrs { const float* w[8]; };

// Wt[z][n][k] = bf16(W[z][k][n])
__global__ void __launch_bounds__(256) conv_wt_kernel(WPtrs wp, bf16* __restrict__ Wt) {
    __shared__ float t[32][33];
    const int z = blockIdx.z;
    const float* W = wp.w[z];
    const int k0 = blockIdx.x * 32, n0 = blockIdx.y * 32;
    const int tx = threadIdx.x & 31, ty = threadIdx.x >> 5;   // 32 x 8
#pragma unroll
    for (int r = 0; r < 4; r++)
        t[ty + r * 8][tx] = W[(size_t)(k0 + ty + r * 8) * 768 + n0 + tx];
    __syncthreads();
    bf16* O = Wt + (size_t)z * 768 * 768;
#pragma unroll
    for (int r = 0; r < 4; r++)
        O[(size_t)(n0 + ty + r * 8) * 768 + k0 + tx] =
            __float2bfloat16(t[tx][ty + r * 8]);
}

// ---------------------------------------------------------------------------
// Batched GEMM bf16: C = A[8192,768] @ Wt^T + bias. Wt is [n][k] bf16.
// BM=128, BN=64, BK=32, 8 warps (4m x 2n), warp tile 32x32, double buffered.
// As/Bs stride 40 bf16 (=20 words, 20g+t conflict-free; rows 80B, 16B-aligned).
// ---------------------------------------------------------------------------
struct GemmBatch {
    const bf16* A[6]; const bf16* W[6]; const float* bias[6]; void* C[6];
};

template <bool OUT_BF16>
__global__ void __launch_bounds__(256) gemm_bf16_kernel(GemmBatch gb) {
    const int z = blockIdx.z;
    const bf16* A = gb.A[z];
    const bf16* W = gb.W[z];
    const float* bias = gb.bias[z];

    __shared__ __align__(16) bf16 As[2][128 * 40];
    __shared__ __align__(16) bf16 Bs[2][64 * 40];

    const int tid = threadIdx.x;
    const int warp = tid >> 5, lane = tid & 31;
    const int gq = lane >> 2, tq = lane & 3;
    const int wm = warp & 3, wn = warp >> 2;
    const int row0 = blockIdx.y * 128, col0 = blockIdx.x * 64;

    const int ar = tid >> 2, ac = (tid & 3) << 3;     // A: +i*64 rows
    const int br = tid >> 2, bc = (tid & 3) << 3;     // B: 64 rows, 1 pass

    auto load_tile = [&](int st, int k0) {
#pragma unroll
        for (int i = 0; i < 2; i++) {
            int r = ar + i * 64;
            cp16(&As[st][r * 40 + ac], A + (size_t)(row0 + r) * 768 + k0 + ac);
        }
        cp16(&Bs[st][br * 40 + bc], W + (size_t)(col0 + br) * 768 + k0 + bc);
    };

    float acc[2][4][4] = {};

    load_tile(0, 0);
    cp_commit();

    for (int kt = 0; kt < 24; kt++) {
        cp_wait0();
        __syncthreads();
        if (kt + 1 < 24) {
            load_tile((kt + 1) & 1, (kt + 1) * 32);
            cp_commit();
        }
        const bf16* Ab = As[kt & 1];
        const bf16* Bb = Bs[kt & 1];
#pragma unroll
        for (int kb = 0; kb < 2; kb++) {
            int kk = kb * 16;
            uint32_t a[2][4];
#pragma unroll
            for (int mi = 0; mi < 2; mi++) {
                int rb = wm * 32 + mi * 16;
                a[mi][0] = *(const uint32_t*)&Ab[(rb + gq) * 40 + kk + 2 * tq];
                a[mi][1] = *(const uint32_t*)&Ab[(rb + 8 + gq) * 40 + kk + 2 * tq];
                a[mi][2] = *(const uint32_t*)&Ab[(rb + gq) * 40 + kk + 8 + 2 * tq];
                a[mi][3] = *(const uint32_t*)&Ab[(rb + 8 + gq) * 40 + kk + 8 + 2 * tq];
            }
#pragma unroll
            for (int ni = 0; ni < 4; ni++) {
                int cb = wn * 32 + ni * 8 + gq;
                uint32_t b0 = *(const uint32_t*)&Bb[cb * 40 + kk + 2 * tq];
                uint32_t b1 = *(const uint32_t*)&Bb[cb * 40 + kk + 8 + 2 * tq];
                mma_bf16(acc[0][ni], a[0], b0, b1);
                mma_bf16(acc[1][ni], a[1], b0, b1);
            }
        }
    }

#pragma unroll
    for (int ni = 0; ni < 4; ni++) {
        int col = col0 + wn * 32 + ni * 8 + 2 * tq;
        float2 bv = *(const float2*)(bias + col);
#pragma unroll
        for (int mi = 0; mi < 2; mi++) {
            int rb = row0 + wm * 32 + mi * 16 + gq;
            if (OUT_BF16) {
                bf16* Cb = (bf16*)gb.C[z];
                *(uint32_t*)&Cb[(size_t)rb * 768 + col] =
                    bf16pack(acc[mi][ni][1] + bv.y, acc[mi][ni][0] + bv.x);
                *(uint32_t*)&Cb[(size_t)(rb + 8) * 768 + col] =
                    bf16pack(acc[mi][ni][3] + bv.y, acc[mi][ni][2] + bv.x);
            } else {
                float* Cf = (float*)gb.C[z];
                *(float2*)(Cf + (size_t)rb * 768 + col) =
                    make_float2(acc[mi][ni][0] + bv.x, acc[mi][ni][1] + bv.y);
                *(float2*)(Cf + (size_t)(rb + 8) * 768 + col) =
                    make_float2(acc[mi][ni][2] + bv.x, acc[mi][ni][3] + bv.y);
            }
        }
    }
}

// ---------------------------------------------------------------------------
// Flash attention bf16. BM=128 (8 warps x 16 rows), BN=64 keys, HD=64.
// Q fragments register-resident (bf16 from GMEM); K/V double-buffered via
// cp.async; P kept in registers (QK C-frag == PV A-frag); V via ldmatrix.trans.
// blockIdx.z = sel*4 + b.
// ---------------------------------------------------------------------------
struct FlashArgs {
    const bf16* Q[2]; const bf16* K[2]; const bf16* V[2];
    const float* mask[2]; bf16* O[2];
};

__global__ void __launch_bounds__(256) flash_bf16_kernel(FlashArgs fa) {
    __shared__ __align__(16) bf16 Ks[2][64 * 72];
    __shared__ __align__(16) bf16 Vs[2][64 * 72];

    const int tid = threadIdx.x;
    const int warp = tid >> 5, lane = tid & 31;
    const int gq = lane >> 2, tq = lane & 3;
    const int sel = blockIdx.z >> 2, b = blockIdx.z & 3;
    const int h = blockIdx.y;
    const int q0 = blockIdx.x * 128;
    const int r0 = warp * 16;

    const bf16* Kbase = fa.K[sel] + ((size_t)(b * S)) * HID + h * HD;
    const bf16* Vbase = fa.V[sel] + ((size_t)(b * S)) * HID + h * HD;
    const float* mb = fa.mask[sel] + (size_t)b * S;

    const int lr = tid >> 3, lc = (tid & 7) << 3;   // 32 rows/pass, 8-elem chunks

    auto load_kv = [&](int st, int k0) {
        const bf16* Kg = Kbase + (size_t)k0 * HID;
        const bf16* Vg = Vbase + (size_t)k0 * HID;
#pragma unroll
        for (int i = 0; i < 2; i++) {
            int r = lr + i * 32;
            cp16(&Ks[st][r * 72 + lc], Kg + (size_t)r * HID + lc);
            cp16(&Vs[st][r * 72 + lc], Vg + (size_t)r * HID + lc);
        }
    };

    // Q fragments: 4 k16-blocks, register-resident.
    uint32_t qf[4][4];
    {
        const bf16* Qb = fa.Q[sel] + ((size_t)(b * S + q0 + r0)) * HID + h * HD;
#pragma unroll
        for (int kb = 0; kb < 4; kb++) {
            int kk = kb * 16;
            qf[kb][0] = *(const uint32_t*)&Qb[(size_t)gq * HID + kk + 2 * tq];
            qf[kb][1] = *(const uint32_t*)&Qb[(size_t)(8 + gq) * HID + kk + 2 * tq];
            qf[kb][2] = *(const uint32_t*)&Qb[(size_t)gq * HID + kk + 8 + 2 * tq];
            qf[kb][3] = *(const uint32_t*)&Qb[(size_t)(8 + gq) * HID + kk + 8 + 2 * tq];
        }
    }

    float m_lo = -1e30f, m_hi = -1e30f, l_lo = 0.f, l_hi = 0.f;
    float o[8][4] = {};

    load_kv(0, 0);
    cp_commit();

    constexpr int NIT = S / 64;
    for (int it = 0; it < NIT; it++) {
        cp_wait0();
        __syncthreads();
        if (it + 1 < NIT) {
            load_kv((it + 1) & 1, (it + 1) * 64);
            cp_commit();
        }
        const bf16* Kb = Ks[it & 1];
        const int k0 = it * 64;

        // S = Q K^T  (K smem is [key][d]: natural B col-major layout)
        float s[8][4] = {};
#pragma unroll
        for (int kb = 0; kb < 4; kb++) {
            int kk = kb * 16;
#pragma unroll
            for (int nf = 0; nf < 8; nf++) {
                uint32_t b0 = *(const uint32_t*)&Kb[(nf * 8 + gq) * 72 + kk + 2 * tq];
                uint32_t b1 = *(const uint32_t*)&Kb[(nf * 8 + gq) * 72 + kk + 8 + 2 * tq];
                mma_bf16(s[nf], qf[kb], b0, b1);
            }
        }

        // online softmax
        float mloc_lo = -1e30f, mloc_hi = -1e30f;
#pragma unroll
        for (int nf = 0; nf < 8; nf++) {
            float2 mv = *(const float2*)(mb + k0 + nf * 8 + 2 * tq);
            s[nf][0] = s[nf][0] * 0.125f + mv.x;
            s[nf][1] = s[nf][1] * 0.125f + mv.y;
            s[nf][2] = s[nf][2] * 0.125f + mv.x;
            s[nf][3] = s[nf][3] * 0.125f + mv.y;
            mloc_lo = fmaxf(mloc_lo, fmaxf(s[nf][0], s[nf][1]));
            mloc_hi = fmaxf(mloc_hi, fmaxf(s[nf][2], s[nf][3]));
        }
        mloc_lo = fmaxf(mloc_lo, __shfl_xor_sync(0xffffffffu, mloc_lo, 1));
        mloc_lo = fmaxf(mloc_lo, __shfl_xor_sync(0xffffffffu, mloc_lo, 2));
        mloc_hi = fmaxf(mloc_hi, __shfl_xor_sync(0xffffffffu, mloc_hi, 1));
        mloc_hi = fmaxf(mloc_hi, __shfl_xor_sync(0xffffffffu, mloc_hi, 2));
        float mn_lo = fmaxf(m_lo, mloc_lo), mn_hi = fmaxf(m_hi, mloc_hi);
        float al_lo = __expf(m_lo - mn_lo), al_hi = __expf(m_hi - mn_hi);

        // exp + pack P into A-fragment registers (no smem!)
        uint32_t pl[8], ph[8];
        float ls_lo = 0.f, ls_hi = 0.f;
#pragma unroll
        for (int nf = 0; nf < 8; nf++) {
            float p0 = __expf(s[nf][0] - mn_lo);
            float p1 = __expf(s[nf][1] - mn_lo);
            float p2 = __expf(s[nf][2] - mn_hi);
            float p3 = __expf(s[nf][3] - mn_hi);
            ls_lo += p0 + p1;
            ls_hi += p2 + p3;
            pl[nf] = bf16pack(p1, p0);
            ph[nf] = bf16pack(p3, p2);
        }
        ls_lo += __shfl_xor_sync(0xffffffffu, ls_lo, 1);
        ls_lo += __shfl_xor_sync(0xffffffffu, ls_lo, 2);
        ls_hi += __shfl_xor_sync(0xffffffffu, ls_hi, 1);
        ls_hi += __shfl_xor_sync(0xffffffffu, ls_hi, 2);
        l_lo = l_lo * al_lo + ls_lo;
        l_hi = l_hi * al_hi + ls_hi;
        m_lo = mn_lo;
        m_hi = mn_hi;
#pragma unroll
        for (int nf = 0; nf < 8; nf++) {
            o[nf][0] *= al_lo; o[nf][1] *= al_lo;
            o[nf][2] *= al_hi; o[nf][3] *= al_hi;
        }

        // O += P V  (V via ldmatrix.x2.trans: smem [key][d] -> B fragments)
        uint32_t v_sh = (uint32_t)__cvta_generic_to_shared(Vs[it & 1]);
#pragma unroll
        for (int j = 0; j < 4; j++) {
            uint32_t rowaddr = v_sh + ((j * 16 + (lane & 15)) * 72) * 2;
            uint32_t a4[4] = {pl[2 * j], ph[2 * j], pl[2 * j + 1], ph[2 * j + 1]};
#pragma unroll
            for (int nf = 0; nf < 8; nf++) {
                uint32_t b0, b1;
                ldsm_x2_trans(b0, b1, rowaddr + nf * 16);
                mma_bf16(o[nf], a4, b0, b1);
            }
        }
    }

    float inv_lo = 1.f / l_lo, inv_hi = 1.f / l_hi;
    bf16* Ob = fa.O[sel] + ((size_t)(b * S + q0)) * HID + h * HD;
#pragma unroll
    for (int nf = 0; nf < 8; nf++) {
        int col = nf * 8 + 2 * tq;
        *(uint32_t*)&Ob[(size_t)(r0 + gq) * HID + col] =
            bf16pack(o[nf][1] * inv_lo, o[nf][0] * inv_lo);
        *(uint32_t*)&Ob[(size_t)(r0 + 8 + gq) * HID + col] =
            bf16pack(o[nf][3] * inv_hi, o[nf][2] * inv_hi);
    }
}

// ---------------------------------------------------------------------------
// out = LayerNorm(T + residual) * g + b. Warp per row, float4, no smem.
// ---------------------------------------------------------------------------
__global__ void __launch_bounds__(256) add_ln_kernel(
    const float* __restrict__ T1, const float* __restrict__ R1,
    const float* __restrict__ g1, const float* __restrict__ b1,
    float* __restrict__ o1,
    const float* __restrict__ T2, const float* __restrict__ R2,
    const float* __restrict__ g2, const float* __restrict__ b2,
    float* __restrict__ o2)
{
    const int st = blockIdx.y;
    const float* T = st ? T2 : T1;
    const float* R = st ? R2 : R1;
    const float* g = st ? g2 : g1;
    const float* bb = st ? b2 : b1;
    float* out = st ? o2 : o1;

    const int warp = threadIdx.x >> 5, lane = threadIdx.x & 31;
    const int row = blockIdx.x * 8 + warp;
    const float* Tr = T + (size_t)row * 768;
    const float* Rr = R + (size_t)row * 768;

    float4 x[6];
    float sum = 0.f, sq = 0.f;
#pragma unroll
    for (int j = 0; j < 6; j++) {
        int c = (j * 32 + lane) * 4;
        float4 t = *(const float4*)(Tr + c);
        float4 r = *(const float4*)(Rr + c);
        x[j] = make_float4(t.x + r.x, t.y + r.y, t.z + r.z, t.w + r.w);
        sum += x[j].x + x[j].y + x[j].z + x[j].w;
        sq += x[j].x * x[j].x + x[j].y * x[j].y +
              x[j].z * x[j].z + x[j].w * x[j].w;
    }
#pragma unroll
    for (int off = 16; off; off >>= 1) {
        sum += __shfl_xor_sync(0xffffffffu, sum, off);
        sq  += __shfl_xor_sync(0xffffffffu, sq,  off);
    }
    float mu = sum * (1.f / 768.f);
    float var = sq * (1.f / 768.f) - mu * mu;
    float rstd = rsqrtf(var + 1e-12f);
#pragma unroll
    for (int j = 0; j < 6; j++) {
        int c = (j * 32 + lane) * 4;
        float4 gv = *(const float4*)(g + c);
        float4 bv = *(const float4*)(bb + c);
        float4 ov;
        ov.x = (x[j].x - mu) * rstd * gv.x + bv.x;
        ov.y = (x[j].y - mu) * rstd * gv.y + bv.y;
        ov.z = (x[j].z - mu) * rstd * gv.z + bv.z;
        ov.w = (x[j].w - mu) * rstd * gv.w + bv.w;
        *(float4*)(out + (size_t)row * 768 + c) = ov;
    }
}

// ---------------------------------------------------------------------------
extern "C" void kernel_launch(void* const* d_in, const int* in_sizes, int n_in,
                              void* d_out, int out_size)
{
    const float* x1    = (const float*)d_in[0];
    const float* mask1 = (const float*)d_in[1];
    const float* x2    = (const float*)d_in[2];
    const float* mask2 = (const float*)d_in[3];
    const float* q1w = (const float*)d_in[4];  const float* q1b = (const float*)d_in[5];
    const float* k1w = (const float*)d_in[6];  const float* k1b = (const float*)d_in[7];
    const float* v1w = (const float*)d_in[8];  const float* v1b = (const float*)d_in[9];
    const float* q2w = (const float*)d_in[10]; const float* q2b = (const float*)d_in[11];
    const float* k2w = (const float*)d_in[12]; const float* k2b = (const float*)d_in[13];
    const float* v2w = (const float*)d_in[14]; const float* v2b = (const float*)d_in[15];
    const float* d1w = (const float*)d_in[16]; const float* d1b = (const float*)d_in[17];
    const float* d2w = (const float*)d_in[18]; const float* d2b = (const float*)d_in[19];
    const float* ln1g = (const float*)d_in[20]; const float* ln1b = (const float*)d_in[21];
    const float* ln2g = (const float*)d_in[22]; const float* ln2b = (const float*)d_in[23];

    void* sp = nullptr;
    cudaGetSymbolAddress(&sp, g_scratch);
    // carve scratch: bf16 region first, f32 region after
    bf16* hb = (bf16*)sp;
    bf16* xb1  = hb + 0 * MAT;
    bf16* xb2  = hb + 1 * MAT;
    bf16* q1   = hb + 2 * MAT;
    bf16* k1   = hb + 3 * MAT;
    bf16* v1   = hb + 4 * MAT;
    bf16* q2   = hb + 5 * MAT;
    bf16* k2   = hb + 6 * MAT;
    bf16* v2   = hb + 7 * MAT;
    bf16* ctx1 = hb + 8 * MAT;
    bf16* ctx2 = hb + 9 * MAT;
    bf16* Wt   = hb + 10 * MAT;                  // 8 x 768 x 768 bf16
    float* t1  = (float*)(hb + 10 * MAT + 8 * 768 * 768);
    float* t2  = t1 + MAT;

    float* out1 = (float*)d_out;
    float* out2 = out1 + MAT;

    // converts
    conv_x_kernel<<<dim3(1024, 2), 256>>>(x1, x2, xb1, xb2);
    WPtrs wp;
    wp.w[0] = q1w; wp.w[1] = k1w; wp.w[2] = v1w;
    wp.w[3] = q2w; wp.w[4] = k2w; wp.w[5] = v2w;
    wp.w[6] = d1w; wp.w[7] = d2w;
    conv_wt_kernel<<<dim3(24, 24, 8), 256>>>(wp, Wt);

    const size_t WSZ = (size_t)768 * 768;

    // 6 input projections, bf16 out
    GemmBatch proj;
    proj.A[0] = xb1; proj.W[0] = Wt + 0 * WSZ; proj.bias[0] = q1b; proj.C[0] = q1;
    proj.A[1] = xb1; proj.W[1] = Wt + 1 * WSZ; proj.bias[1] = k1b; proj.C[1] = k1;
    proj.A[2] = xb1; proj.W[2] = Wt + 2 * WSZ; proj.bias[2] = v1b; proj.C[2] = v1;
    proj.A[3] = xb2; proj.W[3] = Wt + 3 * WSZ; proj.bias[3] = q2b; proj.C[3] = q2;
    proj.A[4] = xb2; proj.W[4] = Wt + 4 * WSZ; proj.bias[4] = k2b; proj.C[4] = k2;
    proj.A[5] = xb2; proj.W[5] = Wt + 5 * WSZ; proj.bias[5] = v2b; proj.C[5] = v2;
    gemm_bf16_kernel<true><<<dim3(12, 64, 6), 256>>>(proj);

    // both attention streams
    FlashArgs fa;
    fa.Q[0] = q2; fa.K[0] = k1; fa.V[0] = v1; fa.mask[0] = mask1; fa.O[0] = ctx1;
    fa.Q[1] = q1; fa.K[1] = k2; fa.V[1] = v2; fa.mask[1] = mask2; fa.O[1] = ctx2;
    flash_bf16_kernel<<<dim3(S / 128, H, 8), 256>>>(fa);

    // 2 output projections, f32 out
    GemmBatch dp;
    dp.A[0] = ctx1; dp.W[0] = Wt + 6 * WSZ; dp.bias[0] = d1b; dp.C[0] = t1;
    dp.A[1] = ctx2; dp.W[1] = Wt + 7 * WSZ; dp.bias[1] = d2b; dp.C[1] = t2;
    for (int i = 2; i < 6; i++) {
        dp.A[i] = nullptr; dp.W[i] = nullptr; dp.bias[i] = nullptr; dp.C[i] = nullptr;
    }
    gemm_bf16_kernel<false><<<dim3(12, 64, 2), 256>>>(dp);

    add_ln_kernel<<<dim3(M / 8, 2), 256>>>(t1, x1, ln1g, ln1b, out1,
                                           t2, x2, ln2g, ln2b, out2);
}

// round 6
// speedup vs baseline: 11.7035x; 1.2118x over previous
#include <cuda_runtime.h>
#include <cuda_bf16.h>
#include <cstdint>

// ---------------------------------------------------------------------------
// BertBiAttention — round 5: flash occupancy 2 CTA/SM + ldmatrix.x4 + ex2.
// B=4, S=2048, HID=768, H=12, HD=64.
// ---------------------------------------------------------------------------

constexpr int B = 4, S = 2048, HID = 768, H = 12, HD = 64;
constexpr int M = B * S;                       // 8192
constexpr size_t MAT = (size_t)M * HID;        // 6.29M elems

__device__ float g_scratch[10 * 6291456];

using bf16 = __nv_bfloat16;

__device__ __forceinline__ void cp16(void* dst_smem, const void* src) {
    uint32_t d = (uint32_t)__cvta_generic_to_shared(dst_smem);
    asm volatile("cp.async.cg.shared.global [%0], [%1], 16;" :: "r"(d), "l"(src));
}
__device__ __forceinline__ void cp_commit() { asm volatile("cp.async.commit_group;"); }
__device__ __forceinline__ void cp_wait0()  { asm volatile("cp.async.wait_group 0;"); }

__device__ __forceinline__ void mma_bf16(float c[4], const uint32_t a[4],
                                         uint32_t b0, uint32_t b1) {
    asm volatile(
        "mma.sync.aligned.m16n8k16.row.col.f32.bf16.bf16.f32 "
        "{%0,%1,%2,%3}, {%4,%5,%6,%7}, {%8,%9}, {%0,%1,%2,%3};"
        : "+f"(c[0]), "+f"(c[1]), "+f"(c[2]), "+f"(c[3])
        : "r"(a[0]), "r"(a[1]), "r"(a[2]), "r"(a[3]), "r"(b0), "r"(b1));
}

// pack: lo -> bits[0:16), hi -> bits[16:32)
__device__ __forceinline__ uint32_t bf16pack(float hi, float lo) {
    uint32_t r;
    asm("cvt.rn.bf16x2.f32 %0, %1, %2;" : "=r"(r) : "f"(hi), "f"(lo));
    return r;
}

__device__ __forceinline__ float ex2(float x) {
    float r;
    asm("ex2.approx.ftz.f32 %0, %1;" : "=f"(r) : "f"(x));
    return r;
}

__device__ __forceinline__ void ldsm_x4(uint32_t& r0, uint32_t& r1,
                                        uint32_t& r2, uint32_t& r3,
                                        uint32_t smem_addr) {
    asm volatile("ldmatrix.sync.aligned.m8n8.x4.shared.b16 {%0,%1,%2,%3}, [%4];"
                 : "=r"(r0), "=r"(r1), "=r"(r2), "=r"(r3) : "r"(smem_addr));
}
__device__ __forceinline__ void ldsm_x4_trans(uint32_t& r0, uint32_t& r1,
                                              uint32_t& r2, uint32_t& r3,
                                              uint32_t smem_addr) {
    asm volatile("ldmatrix.sync.aligned.m8n8.x4.trans.shared.b16 {%0,%1,%2,%3}, [%4];"
                 : "=r"(r0), "=r"(r1), "=r"(r2), "=r"(r3) : "r"(smem_addr));
}

// ---------------------------------------------------------------------------
// Converters
// ---------------------------------------------------------------------------
__global__ void __launch_bounds__(256) conv_x_kernel(
    const float* __restrict__ x1, const float* __restrict__ x2,
    bf16* __restrict__ o1, bf16* __restrict__ o2)
{
    const float* x = blockIdx.y ? x2 : x1;
    bf16* o = blockIdx.y ? o2 : o1;
    const int n4 = (int)(MAT / 4);
    for (int i = blockIdx.x * 256 + threadIdx.x; i < n4; i += gridDim.x * 256) {
        float4 v = *(const float4*)(x + (size_t)i * 4);
        uint32_t lo = bf16pack(v.y, v.x);
        uint32_t hi = bf16pack(v.w, v.z);
        *(uint2*)(o + (size_t)i * 4) = make_uint2(lo, hi);
    }
}

struct WPtrs { const float* w[8]; };

// Wt[z][n][k] = bf16(W[z][k][n])
__global__ void __launch_bounds__(256) conv_wt_kernel(WPtrs wp, bf16* __restrict__ Wt) {
    __shared__ float t[32][33];
    const int z = blockIdx.z;
    const float* W = wp.w[z];
    const int k0 = blockIdx.x * 32, n0 = blockIdx.y * 32;
    const int tx = threadIdx.x & 31, ty = threadIdx.x >> 5;   // 32 x 8
#pragma unroll
    for (int r = 0; r < 4; r++)
        t[ty + r * 8][tx] = W[(size_t)(k0 + ty + r * 8) * 768 + n0 + tx];
    __syncthreads();
    bf16* O = Wt + (size_t)z * 768 * 768;
#pragma unroll
    for (int r = 0; r < 4; r++)
        O[(size_t)(n0 + ty + r * 8) * 768 + k0 + tx] =
            __float2bfloat16(t[tx][ty + r * 8]);
}

// ---------------------------------------------------------------------------
// Batched GEMM bf16: C = A[8192,768] @ Wt^T + bias. Wt is [n][k] bf16.
// BM=128, BN=64, BK=32, 8 warps (4m x 2n), warp tile 32x32, double buffered.
// ---------------------------------------------------------------------------
struct GemmBatch {
    const bf16* A[6]; const bf16* W[6]; const float* bias[6]; void* C[6];
};

template <bool OUT_BF16>
__global__ void __launch_bounds__(256) gemm_bf16_kernel(GemmBatch gb) {
    const int z = blockIdx.z;
    const bf16* A = gb.A[z];
    const bf16* W = gb.W[z];
    const float* bias = gb.bias[z];

    __shared__ __align__(16) bf16 As[2][128 * 40];
    __shared__ __align__(16) bf16 Bs[2][64 * 40];

    const int tid = threadIdx.x;
    const int warp = tid >> 5, lane = tid & 31;
    const int gq = lane >> 2, tq = lane & 3;
    const int wm = warp & 3, wn = warp >> 2;
    const int row0 = blockIdx.y * 128, col0 = blockIdx.x * 64;

    const int ar = tid >> 2, ac = (tid & 3) << 3;     // A: +i*64 rows
    const int br = tid >> 2, bc = (tid & 3) << 3;     // B: 64 rows, 1 pass

    auto load_tile = [&](int st, int k0) {
#pragma unroll
        for (int i = 0; i < 2; i++) {
            int r = ar + i * 64;
            cp16(&As[st][r * 40 + ac], A + (size_t)(row0 + r) * 768 + k0 + ac);
        }
        cp16(&Bs[st][br * 40 + bc], W + (size_t)(col0 + br) * 768 + k0 + bc);
    };

    float acc[2][4][4] = {};

    load_tile(0, 0);
    cp_commit();

    for (int kt = 0; kt < 24; kt++) {
        cp_wait0();
        __syncthreads();
        if (kt + 1 < 24) {
            load_tile((kt + 1) & 1, (kt + 1) * 32);
            cp_commit();
        }
        const bf16* Ab = As[kt & 1];
        const bf16* Bb = Bs[kt & 1];
#pragma unroll
        for (int kb = 0; kb < 2; kb++) {
            int kk = kb * 16;
            uint32_t a[2][4];
#pragma unroll
            for (int mi = 0; mi < 2; mi++) {
                int rb = wm * 32 + mi * 16;
                a[mi][0] = *(const uint32_t*)&Ab[(rb + gq) * 40 + kk + 2 * tq];
                a[mi][1] = *(const uint32_t*)&Ab[(rb + 8 + gq) * 40 + kk + 2 * tq];
                a[mi][2] = *(const uint32_t*)&Ab[(rb + gq) * 40 + kk + 8 + 2 * tq];
                a[mi][3] = *(const uint32_t*)&Ab[(rb + 8 + gq) * 40 + kk + 8 + 2 * tq];
            }
#pragma unroll
            for (int ni = 0; ni < 4; ni++) {
                int cb = wn * 32 + ni * 8 + gq;
                uint32_t b0 = *(const uint32_t*)&Bb[cb * 40 + kk + 2 * tq];
                uint32_t b1 = *(const uint32_t*)&Bb[cb * 40 + kk + 8 + 2 * tq];
                mma_bf16(acc[0][ni], a[0], b0, b1);
                mma_bf16(acc[1][ni], a[1], b0, b1);
            }
        }
    }

#pragma unroll
    for (int ni = 0; ni < 4; ni++) {
        int col = col0 + wn * 32 + ni * 8 + 2 * tq;
        float2 bv = *(const float2*)(bias + col);
#pragma unroll
        for (int mi = 0; mi < 2; mi++) {
            int rb = row0 + wm * 32 + mi * 16 + gq;
            if (OUT_BF16) {
                bf16* Cb = (bf16*)gb.C[z];
                *(uint32_t*)&Cb[(size_t)rb * 768 + col] =
                    bf16pack(acc[mi][ni][1] + bv.y, acc[mi][ni][0] + bv.x);
                *(uint32_t*)&Cb[(size_t)(rb + 8) * 768 + col] =
                    bf16pack(acc[mi][ni][3] + bv.y, acc[mi][ni][2] + bv.x);
            } else {
                float* Cf = (float*)gb.C[z];
                *(float2*)(Cf + (size_t)rb * 768 + col) =
                    make_float2(acc[mi][ni][0] + bv.x, acc[mi][ni][1] + bv.y);
                *(float2*)(Cf + (size_t)(rb + 8) * 768 + col) =
                    make_float2(acc[mi][ni][2] + bv.x, acc[mi][ni][3] + bv.y);
            }
        }
    }
}

// ---------------------------------------------------------------------------
// Flash attention bf16, 2 CTA/SM. BM=128 (8 warps x 16 rows), BN=64, HD=64.
// Q fragments register-resident; K/V double-buffered cp.async; K fragments
// via ldmatrix.x4, V via ldmatrix.x4.trans; P in registers; softmax in
// log2-domain (ex2.approx only, no extra FMUL).
// ---------------------------------------------------------------------------
struct FlashArgs {
    const bf16* Q[2]; const bf16* K[2]; const bf16* V[2];
    const float* mask[2]; bf16* O[2];
};

__global__ void __launch_bounds__(256, 2) flash_bf16_kernel(FlashArgs fa) {
    __shared__ __align__(16) bf16 Ks[2][64 * 72];
    __shared__ __align__(16) bf16 Vs[2][64 * 72];

    const int tid = threadIdx.x;
    const int warp = tid >> 5, lane = tid & 31;
    const int gq = lane >> 2, tq = lane & 3;
    const int sel = blockIdx.z >> 2, b = blockIdx.z & 3;
    const int h = blockIdx.y;
    const int q0 = blockIdx.x * 128;
    const int r0 = warp * 16;

    const bf16* Kbase = fa.K[sel] + ((size_t)(b * S)) * HID + h * HD;
    const bf16* Vbase = fa.V[sel] + ((size_t)(b * S)) * HID + h * HD;
    const float* mb = fa.mask[sel] + (size_t)b * S;

    const int lr = tid >> 3, lc = (tid & 7) << 3;   // 32 rows/pass, 8-elem chunks

    auto load_kv = [&](int st, int k0) {
        const bf16* Kg = Kbase + (size_t)k0 * HID;
        const bf16* Vg = Vbase + (size_t)k0 * HID;
#pragma unroll
        for (int i = 0; i < 2; i++) {
            int r = lr + i * 32;
            cp16(&Ks[st][r * 72 + lc], Kg + (size_t)r * HID + lc);
            cp16(&Vs[st][r * 72 + lc], Vg + (size_t)r * HID + lc);
        }
    };

    // Q fragments: 4 k16-blocks, register-resident.
    uint32_t qf[4][4];
    {
        const bf16* Qb = fa.Q[sel] + ((size_t)(b * S + q0 + r0)) * HID + h * HD;
#pragma unroll
        for (int kb = 0; kb < 4; kb++) {
            int kk = kb * 16;
            qf[kb][0] = *(const uint32_t*)&Qb[(size_t)gq * HID + kk + 2 * tq];
            qf[kb][1] = *(const uint32_t*)&Qb[(size_t)(8 + gq) * HID + kk + 2 * tq];
            qf[kb][2] = *(const uint32_t*)&Qb[(size_t)gq * HID + kk + 8 + 2 * tq];
            qf[kb][3] = *(const uint32_t*)&Qb[(size_t)(8 + gq) * HID + kk + 8 + 2 * tq];
        }
    }

    // log2-domain softmax constants: scores scaled by 0.125*log2(e)
    const float C1 = 0.125f * 1.4426950408889634f;
    const float LOG2E = 1.4426950408889634f;

    float m_lo = -1e30f, m_hi = -1e30f, l_lo = 0.f, l_hi = 0.f;
    float o[8][4] = {};

    load_kv(0, 0);
    cp_commit();

    constexpr int NIT = S / 64;
    for (int it = 0; it < NIT; it++) {
        cp_wait0();
        __syncthreads();
        if (it + 1 < NIT) {
            load_kv((it + 1) & 1, (it + 1) * 64);
            cp_commit();
        }
        const int k0 = it * 64;

        // S = Q K^T — K B-fragments via ldmatrix.x4 (non-trans).
        // lane L -> row nf*8 + (L&7), k-block m = (L>>3)&3 at col m*8.
        float s[8][4] = {};
        {
            uint32_t k_sh = (uint32_t)__cvta_generic_to_shared(Ks[it & 1]);
            uint32_t base = k_sh +
                (((lane & 7) * 72) + ((lane >> 3) & 3) * 8) * 2;
#pragma unroll
            for (int nf = 0; nf < 8; nf++) {
                uint32_t addr = base + nf * 8 * 72 * 2;
                uint32_t b0, b1, b2, b3, b4, b5, b6, b7;
                ldsm_x4(b0, b1, b2, b3, addr);          // k 0..31
                ldsm_x4(b4, b5, b6, b7, addr + 64);     // k 32..63
                mma_bf16(s[nf], qf[0], b0, b1);
                mma_bf16(s[nf], qf[1], b2, b3);
                mma_bf16(s[nf], qf[2], b4, b5);
                mma_bf16(s[nf], qf[3], b6, b7);
            }
        }

        // online softmax in log2 domain
        float mloc_lo = -1e30f, mloc_hi = -1e30f;
#pragma unroll
        for (int nf = 0; nf < 8; nf++) {
            float2 mv = *(const float2*)(mb + k0 + nf * 8 + 2 * tq);
            float mvx = mv.x * LOG2E, mvy = mv.y * LOG2E;
            s[nf][0] = fmaf(s[nf][0], C1, mvx);
            s[nf][1] = fmaf(s[nf][1], C1, mvy);
            s[nf][2] = fmaf(s[nf][2], C1, mvx);
            s[nf][3] = fmaf(s[nf][3], C1, mvy);
            mloc_lo = fmaxf(mloc_lo, fmaxf(s[nf][0], s[nf][1]));
            mloc_hi = fmaxf(mloc_hi, fmaxf(s[nf][2], s[nf][3]));
        }
        mloc_lo = fmaxf(mloc_lo, __shfl_xor_sync(0xffffffffu, mloc_lo, 1));
        mloc_lo = fmaxf(mloc_lo, __shfl_xor_sync(0xffffffffu, mloc_lo, 2));
        mloc_hi = fmaxf(mloc_hi, __shfl_xor_sync(0xffffffffu, mloc_hi, 1));
        mloc_hi = fmaxf(mloc_hi, __shfl_xor_sync(0xffffffffu, mloc_hi, 2));
        float mn_lo = fmaxf(m_lo, mloc_lo), mn_hi = fmaxf(m_hi, mloc_hi);
        float al_lo = ex2(m_lo - mn_lo), al_hi = ex2(m_hi - mn_hi);

        // exp2 + pack P into A-fragment registers
        uint32_t pl[8], ph[8];
        float ls_lo = 0.f, ls_hi = 0.f;
#pragma unroll
        for (int nf = 0; nf < 8; nf++) {
            float p0 = ex2(s[nf][0] - mn_lo);
            float p1 = ex2(s[nf][1] - mn_lo);
            float p2 = ex2(s[nf][2] - mn_hi);
            float p3 = ex2(s[nf][3] - mn_hi);
            ls_lo += p0 + p1;
            ls_hi += p2 + p3;
            pl[nf] = bf16pack(p1, p0);
            ph[nf] = bf16pack(p3, p2);
        }
        ls_lo += __shfl_xor_sync(0xffffffffu, ls_lo, 1);
        ls_lo += __shfl_xor_sync(0xffffffffu, ls_lo, 2);
        ls_hi += __shfl_xor_sync(0xffffffffu, ls_hi, 1);
        ls_hi += __shfl_xor_sync(0xffffffffu, ls_hi, 2);
        l_lo = l_lo * al_lo + ls_lo;
        l_hi = l_hi * al_hi + ls_hi;
        m_lo = mn_lo;
        m_hi = mn_hi;
#pragma unroll
        for (int nf = 0; nf < 8; nf++) {
            o[nf][0] *= al_lo; o[nf][1] *= al_lo;
            o[nf][2] *= al_hi; o[nf][3] *= al_hi;
        }

        // O += P V — V B-fragments via ldmatrix.x4.trans (2 nf per load).
        // lane L -> row j*16 + ((L>>3)&1)*8 + (L&7), col (2nfp + (L>>4))*8.
        {
            uint32_t v_sh = (uint32_t)__cvta_generic_to_shared(Vs[it & 1]);
            uint32_t base = v_sh +
                (((((lane >> 3) & 1) * 8 + (lane & 7)) * 72) + (lane >> 4) * 8) * 2;
#pragma unroll
            for (int j = 0; j < 4; j++) {
                uint32_t a4[4] = {pl[2 * j], ph[2 * j], pl[2 * j + 1], ph[2 * j + 1]};
                uint32_t rowbase = base + j * 16 * 72 * 2;
#pragma unroll
                for (int nfp = 0; nfp < 4; nfp++) {
                    uint32_t b0, b1, b2, b3;
                    ldsm_x4_trans(b0, b1, b2, b3, rowbase + nfp * 32);
                    mma_bf16(o[2 * nfp], a4, b0, b1);
                    mma_bf16(o[2 * nfp + 1], a4, b2, b3);
                }
            }
        }
    }

    float inv_lo = 1.f / l_lo, inv_hi = 1.f / l_hi;
    bf16* Ob = fa.O[sel] + ((size_t)(b * S + q0)) * HID + h * HD;
#pragma unroll
    for (int nf = 0; nf < 8; nf++) {
        int col = nf * 8 + 2 * tq;
        *(uint32_t*)&Ob[(size_t)(r0 + gq) * HID + col] =
            bf16pack(o[nf][1] * inv_lo, o[nf][0] * inv_lo);
        *(uint32_t*)&Ob[(size_t)(r0 + 8 + gq) * HID + col] =
            bf16pack(o[nf][3] * inv_hi, o[nf][2] * inv_hi);
    }
}

// ---------------------------------------------------------------------------
// out = LayerNorm(T + residual) * g + b. Warp per row, float4, no smem.
// ---------------------------------------------------------------------------
__global__ void __launch_bounds__(256) add_ln_kernel(
    const float* __restrict__ T1, const float* __restrict__ R1,
    const float* __restrict__ g1, const float* __restrict__ b1,
    float* __restrict__ o1,
    const float* __restrict__ T2, const float* __restrict__ R2,
    const float* __restrict__ g2, const float* __restrict__ b2,
    float* __restrict__ o2)
{
    const int st = blockIdx.y;
    const float* T = st ? T2 : T1;
    const float* R = st ? R2 : R1;
    const float* g = st ? g2 : g1;
    const float* bb = st ? b2 : b1;
    float* out = st ? o2 : o1;

    const int warp = threadIdx.x >> 5, lane = threadIdx.x & 31;
    const int row = blockIdx.x * 8 + warp;
    const float* Tr = T + (size_t)row * 768;
    const float* Rr = R + (size_t)row * 768;

    float4 x[6];
    float sum = 0.f, sq = 0.f;
#pragma unroll
    for (int j = 0; j < 6; j++) {
        int c = (j * 32 + lane) * 4;
        float4 t = *(const float4*)(Tr + c);
        float4 r = *(const float4*)(Rr + c);
        x[j] = make_float4(t.x + r.x, t.y + r.y, t.z + r.z, t.w + r.w);
        sum += x[j].x + x[j].y + x[j].z + x[j].w;
        sq += x[j].x * x[j].x + x[j].y * x[j].y +
              x[j].z * x[j].z + x[j].w * x[j].w;
    }
#pragma unroll
    for (int off = 16; off; off >>= 1) {
        sum += __shfl_xor_sync(0xffffffffu, sum, off);
        sq  += __shfl_xor_sync(0xffffffffu, sq,  off);
    }
    float mu = sum * (1.f / 768.f);
    float var = sq * (1.f / 768.f) - mu * mu;
    float rstd = rsqrtf(var + 1e-12f);
#pragma unroll
    for (int j = 0; j < 6; j++) {
        int c = (j * 32 + lane) * 4;
        float4 gv = *(const float4*)(g + c);
        float4 bv = *(const float4*)(bb + c);
        float4 ov;
        ov.x = (x[j].x - mu) * rstd * gv.x + bv.x;
        ov.y = (x[j].y - mu) * rstd * gv.y + bv.y;
        ov.z = (x[j].z - mu) * rstd * gv.z + bv.z;
        ov.w = (x[j].w - mu) * rstd * gv.w + bv.w;
        *(float4*)(out + (size_t)row * 768 + c) = ov;
    }
}

// ---------------------------------------------------------------------------
extern "C" void kernel_launch(void* const* d_in, const int* in_sizes, int n_in,
                              void* d_out, int out_size)
{
    const float* x1    = (const float*)d_in[0];
    const float* mask1 = (const float*)d_in[1];
    const float* x2    = (const float*)d_in[2];
    const float* mask2 = (const float*)d_in[3];
    const float* q1w = (const float*)d_in[4];  const float* q1b = (const float*)d_in[5];
    const float* k1w = (const float*)d_in[6];  const float* k1b = (const float*)d_in[7];
    const float* v1w = (const float*)d_in[8];  const float* v1b = (const float*)d_in[9];
    const float* q2w = (const float*)d_in[10]; const float* q2b = (const float*)d_in[11];
    const float* k2w = (const float*)d_in[12]; const float* k2b = (const float*)d_in[13];
    const float* v2w = (const float*)d_in[14]; const float* v2b = (const float*)d_in[15];
    const float* d1w = (const float*)d_in[16]; const float* d1b = (const float*)d_in[17];
    const float* d2w = (const float*)d_in[18]; const float* d2b = (const float*)d_in[19];
    const float* ln1g = (const float*)d_in[20]; const float* ln1b = (const float*)d_in[21];
    const float* ln2g = (const float*)d_in[22]; const float* ln2b = (const float*)d_in[23];

    void* sp = nullptr;
    cudaGetSymbolAddress(&sp, g_scratch);
    bf16* hb = (bf16*)sp;
    bf16* xb1  = hb + 0 * MAT;
    bf16* xb2  = hb + 1 * MAT;
    bf16* q1   = hb + 2 * MAT;
    bf16* k1   = hb + 3 * MAT;
    bf16* v1   = hb + 4 * MAT;
    bf16* q2   = hb + 5 * MAT;
    bf16* k2   = hb + 6 * MAT;
    bf16* v2   = hb + 7 * MAT;
    bf16* ctx1 = hb + 8 * MAT;
    bf16* ctx2 = hb + 9 * MAT;
    bf16* Wt   = hb + 10 * MAT;                  // 8 x 768 x 768 bf16
    float* t1  = (float*)(hb + 10 * MAT + 8 * 768 * 768);
    float* t2  = t1 + MAT;

    float* out1 = (float*)d_out;
    float* out2 = out1 + MAT;

    // converts
    conv_x_kernel<<<dim3(1024, 2), 256>>>(x1, x2, xb1, xb2);
    WPtrs wp;
    wp.w[0] = q1w; wp.w[1] = k1w; wp.w[2] = v1w;
    wp.w[3] = q2w; wp.w[4] = k2w; wp.w[5] = v2w;
    wp.w[6] = d1w; wp.w[7] = d2w;
    conv_wt_kernel<<<dim3(24, 24, 8), 256>>>(wp, Wt);

    const size_t WSZ = (size_t)768 * 768;

    // 6 input projections, bf16 out
    GemmBatch proj;
    proj.A[0] = xb1; proj.W[0] = Wt + 0 * WSZ; proj.bias[0] = q1b; proj.C[0] = q1;
    proj.A[1] = xb1; proj.W[1] = Wt + 1 * WSZ; proj.bias[1] = k1b; proj.C[1] = k1;
    proj.A[2] = xb1; proj.W[2] = Wt + 2 * WSZ; proj.bias[2] = v1b; proj.C[2] = v1;
    proj.A[3] = xb2; proj.W[3] = Wt + 3 * WSZ; proj.bias[3] = q2b; proj.C[3] = q2;
    proj.A[4] = xb2; proj.W[4] = Wt + 4 * WSZ; proj.bias[4] = k2b; proj.C[4] = k2;
    proj.A[5] = xb2; proj.W[5] = Wt + 5 * WSZ; proj.bias[5] = v2b; proj.C[5] = v2;
    gemm_bf16_kernel<true><<<dim3(12, 64, 6), 256>>>(proj);

    // both attention streams
    FlashArgs fa;
    fa.Q[0] = q2; fa.K[0] = k1; fa.V[0] = v1; fa.mask[0] = mask1; fa.O[0] = ctx1;
    fa.Q[1] = q1; fa.K[1] = k2; fa.V[1] = v2; fa.mask[1] = mask2; fa.O[1] = ctx2;
    flash_bf16_kernel<<<dim3(S / 128, H, 8), 256>>>(fa);

    // 2 output projections, f32 out
    GemmBatch dp;
    dp.A[0] = ctx1; dp.W[0] = Wt + 6 * WSZ; dp.bias[0] = d1b; dp.C[0] = t1;
    dp.A[1] = ctx2; dp.W[1] = Wt + 7 * WSZ; dp.bias[1] = d2b; dp.C[1] = t2;
    for (int i = 2; i < 6; i++) {
        dp.A[i] = nullptr; dp.W[i] = nullptr; dp.bias[i] = nullptr; dp.C[i] = nullptr;
    }
    gemm_bf16_kernel<false><<<dim3(12, 64, 2), 256>>>(dp);

    add_ln_kernel<<<dim3(M / 8, 2), 256>>>(t1, x1, ln1g, ln1b, out1,
                                           t2, x2, ln2g, ln2b, out2);
}